// round 9
// baseline (speedup 1.0000x reference)
#include <cuda_runtime.h>
#include <math.h>
#include <stdint.h>

// ===================== dims =====================
enum : int {
    NIMG = 128, IMG_H = 72, IMG_W = 128,
    C1_OC = 256, C1_H = 33, C1_W = 61, C1_POS = NIMG * C1_H * C1_W,   // 257664
    P1_H = 15, P1_W = 29,
    C2_OC = 128, C2_H = 6, C2_W = 13, C2_POS = NIMG * C2_H * C2_W,    // 9984
    C3_OC = 128, C3_H = 5, C3_W = 12, C3_POS = NIMG * C3_H * C3_W,    // 7680
    FC1_N = 4096, FC1_K = 7680,
    HID = 2048, GATE = 8192,
    TSTEPS = 32, BATCH = 4,
};

// ===================== scratch (device globals; allocation-free) =====================
__device__ __align__(16) float g_A1[C1_POS * 64];                 // im2col conv1
__device__ __align__(16) float g_C1[(size_t)C1_POS * C1_OC];      // conv1 out [pos][oc]
__device__ __align__(16) float g_P1[NIMG * P1_H * P1_W * 256];    // pooled NHWC
__device__ __align__(16) float g_A2[(size_t)C2_POS * 4096];       // im2col conv2
__device__ __align__(16) float g_C2[C2_POS * 128];
__device__ __align__(16) float g_A3[C3_POS * 512];
__device__ __align__(16) float g_C3[C3_POS * 128];
__device__ __align__(16) float g_F [NIMG * FC1_K];
__device__ __align__(16) float g_H1[NIMG * 4096];
__device__ __align__(16) float g_H2[NIMG * 4096];
__device__ __align__(16) float g_G0[NIMG * GATE];
__device__ __align__(16) float g_gates[BATCH * GATE];
__device__ __align__(16) float g_h[BATCH * HID];
__device__ __align__(16) float g_c[BATCH * HID];
__device__ __align__(16) float g_hid[NIMG * HID];
__device__ __align__(16) float g_b1[NIMG * 2048];                 // merged actor|critic layer1
__device__ __align__(16) float g_b2[NIMG * 1024];                 // merged actor|critic layer2
__device__ __align__(16) float g_w2t[128 * 16 * 256];             // conv2_w -> [oc][pq][c]
__device__ __align__(16) float g_w3t[128 * 4 * 128];              // conv3_w -> [oc][pq][c]
__device__ __align__(16) float g_cb[GATE];                        // bih + bhh
__device__ __align__(16) float g_part[(size_t)4 * C2_POS * 128];  // split-K partials (max case)

__device__ __forceinline__ float leakyf(float z) { return z > 0.f ? z : 0.01f * z; }
__device__ __forceinline__ uint32_t f2tf(float x) {
    uint32_t r; asm("cvt.rna.tf32.f32 %0, %1;" : "=r"(r) : "f"(x)); return r;
}
__device__ __forceinline__ void split_tf32(float v, uint32_t& hi, uint32_t& lo) {
    hi = f2tf(v);
    lo = f2tf(v - __uint_as_float(hi));
}
__device__ __forceinline__ void mma_tf32(float& c0, float& c1, float& c2, float& c3,
                                         uint32_t a0, uint32_t a1, uint32_t a2, uint32_t a3,
                                         uint32_t b0, uint32_t b1)
{
    asm volatile("mma.sync.aligned.m16n8k8.row.col.f32.tf32.tf32.f32 "
                 "{%0,%1,%2,%3}, {%4,%5,%6,%7}, {%8,%9}, {%0,%1,%2,%3};"
                 : "+f"(c0), "+f"(c1), "+f"(c2), "+f"(c3)
                 : "r"(a0), "r"(a1), "r"(a2), "r"(a3), "r"(b0), "r"(b1));
}

// ===================== 3xTF32 tensor-core GEMM: C[M,N] = A[M,K] * B[N,K]^T =====================
// CTA tile 128x128 (8 warps, 2x4), warp tile 64x32 (4x4 m16n8k8 frags), k-chunk 16.
// hi/lo tf32 split; acc += a_hi*b_hi + a_hi*b_lo + a_lo*b_hi (~22-bit effective mantissa).
// SMEM stores each 8-k group as pairs (k, k+4) at words (2j, 2j+1) so each fragment
// fetch (k=ko+tg, ko+tg+4) is a single LDS.64. Pass order ah*bh -> ah*bl -> al*bh
// keeps bh fragments resident in registers across passes.
// lda/ldb = row strides (>= K). Dual-operand: blocks with blockIdx.x >= xHalf use
// A2/B2/bias2 (B2/bias2 pre-adjusted by caller so global col indexing works).
// Split-K: blockIdx.z = chunk; writes raw partial at C + z*M*N when nSplit>1.
__global__ void __launch_bounds__(256, 2) tgemm_k(
    const float* __restrict__ A, const float* __restrict__ B, float* __restrict__ C,
    int M, int N, int K, int lda, int ldb, int Kc, int nSplit,
    const float* __restrict__ bias, int act,
    const float* __restrict__ A2, const float* __restrict__ B2,
    const float* __restrict__ bias2, int xHalf)
{
    __shared__ uint32_t Ah[128][20];   // paired-k layout, +4 pad
    __shared__ uint32_t Al[128][20];
    __shared__ uint32_t Bh[128][20];
    __shared__ uint32_t Bl[128][20];

    const int s = blockIdx.z;
    const int tid = threadIdx.x;
    const int warp = tid >> 5, lane = tid & 31;
    const int g = lane >> 2, tg = lane & 3;
    const int wm = (warp >> 2) * 64;
    const int wn = (warp & 3) * 32;

    const int sm = tid >> 1;                    // staging row 0..127
    const int sk = (tid & 1) * 8;               // staging k offset 0 or 8

    const float* Abase = (A2 && blockIdx.x >= xHalf) ? A2 : A;
    const float* Bbase = (B2 && blockIdx.x >= xHalf) ? B2 : B;
    const float* biasUse = (bias2 && blockIdx.x >= xHalf) ? bias2 : bias;

    const float* Ap = Abase + (size_t)s * Kc + (size_t)(blockIdx.y * 128 + sm) * lda + sk;
    const float* Bp = Bbase + (size_t)s * Kc + (size_t)(blockIdx.x * 128 + sm) * ldb + sk;

    float acc[4][4][4];
#pragma unroll
    for (int i = 0; i < 4; i++)
#pragma unroll
        for (int j = 0; j < 4; j++)
#pragma unroll
            for (int r = 0; r < 4; r++) acc[i][j][r] = 0.f;

    // preload stage 0
    float4 va0 = *(const float4*)(Ap);
    float4 va1 = *(const float4*)(Ap + 4);
    float4 vb0 = *(const float4*)(Bp);
    float4 vb1 = *(const float4*)(Bp + 4);

    for (int k0 = 0; k0 < Kc; k0 += 16) {
        __syncthreads();   // protect previous stage's smem reads
        {
            uint32_t h[8], l[8];
            split_tf32(va0.x, h[0], l[0]); split_tf32(va0.y, h[1], l[1]);
            split_tf32(va0.z, h[2], l[2]); split_tf32(va0.w, h[3], l[3]);
            split_tf32(va1.x, h[4], l[4]); split_tf32(va1.y, h[5], l[5]);
            split_tf32(va1.z, h[6], l[6]); split_tf32(va1.w, h[7], l[7]);
#pragma unroll
            for (int j = 0; j < 4; j++) {
                *(uint2*)&Ah[sm][sk + 2 * j] = make_uint2(h[j], h[j + 4]);
                *(uint2*)&Al[sm][sk + 2 * j] = make_uint2(l[j], l[j + 4]);
            }
            split_tf32(vb0.x, h[0], l[0]); split_tf32(vb0.y, h[1], l[1]);
            split_tf32(vb0.z, h[2], l[2]); split_tf32(vb0.w, h[3], l[3]);
            split_tf32(vb1.x, h[4], l[4]); split_tf32(vb1.y, h[5], l[5]);
            split_tf32(vb1.z, h[6], l[6]); split_tf32(vb1.w, h[7], l[7]);
#pragma unroll
            for (int j = 0; j < 4; j++) {
                *(uint2*)&Bh[sm][sk + 2 * j] = make_uint2(h[j], h[j + 4]);
                *(uint2*)&Bl[sm][sk + 2 * j] = make_uint2(l[j], l[j + 4]);
            }
        }
        __syncthreads();

        if (k0 + 16 < Kc) {   // prefetch next stage, overlapped with mma below
            va0 = *(const float4*)(Ap + k0 + 16);
            va1 = *(const float4*)(Ap + k0 + 20);
            vb0 = *(const float4*)(Bp + k0 + 16);
            vb1 = *(const float4*)(Bp + k0 + 20);
        }

#pragma unroll
        for (int ko = 0; ko < 16; ko += 8) {
            uint2 a0[4], a1[4], bh[4], bx[4];
            // ---- load a_hi + b_hi frags (LDS.64 each) ----
#pragma unroll
            for (int mf = 0; mf < 4; mf++) {
                int r0 = wm + mf * 16 + g;
                a0[mf] = *(const uint2*)&Ah[r0][ko + 2 * tg];
                a1[mf] = *(const uint2*)&Ah[r0 + 8][ko + 2 * tg];
            }
#pragma unroll
            for (int nf = 0; nf < 4; nf++) {
                int n0 = wn + nf * 8 + g;
                bh[nf] = *(const uint2*)&Bh[n0][ko + 2 * tg];
            }
            // ---- pass 1: a_hi * b_hi ----
#pragma unroll
            for (int mf = 0; mf < 4; mf++)
#pragma unroll
                for (int nf = 0; nf < 4; nf++)
                    mma_tf32(acc[mf][nf][0], acc[mf][nf][1], acc[mf][nf][2], acc[mf][nf][3],
                             a0[mf].x, a1[mf].x, a0[mf].y, a1[mf].y, bh[nf].x, bh[nf].y);
            // ---- pass 2: a_hi * b_lo ----
#pragma unroll
            for (int nf = 0; nf < 4; nf++) {
                int n0 = wn + nf * 8 + g;
                bx[nf] = *(const uint2*)&Bl[n0][ko + 2 * tg];
            }
#pragma unroll
            for (int mf = 0; mf < 4; mf++)
#pragma unroll
                for (int nf = 0; nf < 4; nf++)
                    mma_tf32(acc[mf][nf][0], acc[mf][nf][1], acc[mf][nf][2], acc[mf][nf][3],
                             a0[mf].x, a1[mf].x, a0[mf].y, a1[mf].y, bx[nf].x, bx[nf].y);
            // ---- pass 3: a_lo * b_hi (bh reused from registers) ----
#pragma unroll
            for (int mf = 0; mf < 4; mf++) {
                int r0 = wm + mf * 16 + g;
                a0[mf] = *(const uint2*)&Al[r0][ko + 2 * tg];
                a1[mf] = *(const uint2*)&Al[r0 + 8][ko + 2 * tg];
            }
#pragma unroll
            for (int mf = 0; mf < 4; mf++)
#pragma unroll
                for (int nf = 0; nf < 4; nf++)
                    mma_tf32(acc[mf][nf][0], acc[mf][nf][1], acc[mf][nf][2], acc[mf][nf][3],
                             a0[mf].x, a1[mf].x, a0[mf].y, a1[mf].y, bh[nf].x, bh[nf].y);
        }
    }

    // epilogue
    const int rowBase = blockIdx.y * 128 + wm + g;
    const int colBase = blockIdx.x * 128 + wn + tg * 2;
    if (nSplit > 1) {
        float* Cp = C + (size_t)s * M * N;
#pragma unroll
        for (int mf = 0; mf < 4; mf++)
#pragma unroll
            for (int nf = 0; nf < 4; nf++) {
                int row = rowBase + mf * 16;
                int col = colBase + nf * 8;
                *(float2*)&Cp[(size_t)row * N + col]       = make_float2(acc[mf][nf][0], acc[mf][nf][1]);
                *(float2*)&Cp[(size_t)(row + 8) * N + col] = make_float2(acc[mf][nf][2], acc[mf][nf][3]);
            }
    } else {
#pragma unroll
        for (int mf = 0; mf < 4; mf++)
#pragma unroll
            for (int nf = 0; nf < 4; nf++) {
                int row = rowBase + mf * 16;
                int col = colBase + nf * 8;
                float v0 = acc[mf][nf][0], v1 = acc[mf][nf][1];
                float v2 = acc[mf][nf][2], v3 = acc[mf][nf][3];
                if (biasUse) {
                    float b0 = biasUse[col], b1 = biasUse[col + 1];
                    v0 += b0; v1 += b1; v2 += b0; v3 += b1;
                }
                if (act) { v0 = leakyf(v0); v1 = leakyf(v1); v2 = leakyf(v2); v3 = leakyf(v3); }
                *(float2*)&C[(size_t)row * N + col]       = make_float2(v0, v1);
                *(float2*)&C[(size_t)(row + 8) * N + col] = make_float2(v2, v3);
            }
    }
}

__global__ void reduce_k(const float* __restrict__ P, float* __restrict__ C,
                         int MN, int N, int S, const float* __restrict__ bias, int act,
                         const float* __restrict__ bias2, int colSplit)
{
    int idx = blockIdx.x * 256 + threadIdx.x;
    if (idx >= MN) return;
    float v = 0.f;
    for (int s = 0; s < S; s++) v += P[(size_t)s * MN + idx];
    int col = idx % N;
    if (bias2 && col >= colSplit) v += bias2[col - colSplit];
    else if (bias) v += bias[col];
    if (act) v = leakyf(v);
    C[idx] = v;
}

// ===================== layer-specific kernels =====================
__global__ void im2col1_k(const float* __restrict__ x)
{
    int idx = blockIdx.x * 256 + threadIdx.x;
    if (idx >= C1_POS * 64) return;
    int k = idx & 63, pos = idx >> 6;
    int j = pos % C1_W, t = pos / C1_W;
    int i = t % C1_H, n = t / C1_H;
    int p = k >> 3, q = k & 7;
    g_A1[idx] = x[((size_t)n * IMG_H + (2 * i + p)) * IMG_W + (2 * j + q)] * (1.f / 255.f);
}

__global__ void pool1_k(const float* __restrict__ conv1_b)
{
    int idx = blockIdx.x * 256 + threadIdx.x;                 // NHWC output
    if (idx >= NIMG * P1_H * P1_W * 256) return;
    int c = idx & 255, r = idx >> 8;
    int x = r % P1_W; r /= P1_W;
    int y = r % P1_H; int n = r / P1_H;
    float m = -3.4e38f;
#pragma unroll
    for (int p = 0; p < 4; p++)
#pragma unroll
        for (int q = 0; q < 4; q++) {
            int pos = (n * C1_H + 2 * y + p) * C1_W + (2 * x + q);
            float v = g_C1[(size_t)pos * 256 + c];
            m = fmaxf(m, v);
        }
    g_P1[idx] = leakyf(m + conv1_b[c]);
}

__global__ void w2t_k(const float* __restrict__ w) // [oc][c][pq] -> [oc][pq][c]
{
    int idx = blockIdx.x * 256 + threadIdx.x;
    if (idx >= 128 * 16 * 256) return;
    int c = idx & 255, r = idx >> 8;
    int pq = r & 15, oc = r >> 4;
    g_w2t[idx] = w[((size_t)oc * 256 + c) * 16 + pq];
}

__global__ void w3t_k(const float* __restrict__ w)
{
    int idx = blockIdx.x * 256 + threadIdx.x;
    if (idx >= 128 * 4 * 128) return;
    int c = idx & 127, r = idx >> 7;
    int pq = r & 3, oc = r >> 2;
    g_w3t[idx] = w[((size_t)oc * 128 + c) * 4 + pq];
}

__global__ void im2col2_k()
{
    int idx = blockIdx.x * 256 + threadIdx.x;
    if (idx >= C2_POS * 4096) return;
    int c = idx & 255, r = idx >> 8;
    int pq = r & 15, pos2 = r >> 4;
    int p = pq >> 2, q = pq & 3;
    int n = pos2 / (C2_H * C2_W), rem = pos2 % (C2_H * C2_W);
    int i = rem / C2_W, j = rem % C2_W;
    g_A2[idx] = g_P1[(((size_t)n * P1_H + (2 * i + p)) * P1_W + (2 * j + q)) * 256 + c];
}

__global__ void im2col3_k()
{
    int idx = blockIdx.x * 256 + threadIdx.x;
    if (idx >= C3_POS * 512) return;
    int c = idx & 127, r = idx >> 7;
    int pq = r & 3, pos3 = r >> 2;
    int p = pq >> 1, q = pq & 1;
    int n = pos3 / (C3_H * C3_W), rem = pos3 % (C3_H * C3_W);
    int i = rem / C3_W, j = rem % C3_W;
    g_A3[idx] = g_C2[((size_t)(n * C2_H + i + p) * C2_W + (j + q)) * 128 + c];
}

__global__ void flatten_k() // [pos][c] -> [n][c*60 + i*12 + j]
{
    int idx = blockIdx.x * 256 + threadIdx.x;
    if (idx >= NIMG * FC1_K) return;
    int n = idx / FC1_K, r = idx % FC1_K;
    int c = r / 60, t = r % 60;
    int i = t / 12, j = t % 12;
    g_F[idx] = g_C3[(size_t)((n * C3_H + i) * C3_W + j) * 128 + c];
}

__global__ void cbias_k(const float* __restrict__ bih, const float* __restrict__ bhh)
{
    int i = blockIdx.x * 256 + threadIdx.x;
    if (i < GATE) g_cb[i] = bih[i] + bhh[i];
}

__global__ void init_hc_k(const float* __restrict__ h0, const float* __restrict__ c0)
{
    int i = blockIdx.x * 256 + threadIdx.x;
    if (i < BATCH * HID) { g_h[i] = h0[i]; g_c[i] = c0[i]; }
}

// gates[b][j] = G0[t*4+b][j] + dot(whh[j], h[b]*mask[b])   — warp per j, 8 j per block
__global__ void __launch_bounds__(256) lstm_gates_k(const float* __restrict__ whh,
                                                    const float* __restrict__ done, int t)
{
    __shared__ float4 hs[BATCH * 512];
    int tid = threadIdx.x;
    float m0 = 1.f - done[t * 4 + 0];
    float m1 = 1.f - done[t * 4 + 1];
    float m2 = 1.f - done[t * 4 + 2];
    float m3 = 1.f - done[t * 4 + 3];
    const float4* h4 = (const float4*)g_h;
    for (int u = tid; u < BATCH * 512; u += 256) {
        int b = u >> 9;
        float mb = (b == 0) ? m0 : (b == 1) ? m1 : (b == 2) ? m2 : m3;
        float4 v = h4[u];
        v.x *= mb; v.y *= mb; v.z *= mb; v.w *= mb;
        hs[u] = v;
    }
    __syncthreads();
    int warp = tid >> 5, lane = tid & 31;
    int j = blockIdx.x * 8 + warp;
    const float4* w = (const float4*)(whh + (size_t)j * HID);
    float s0 = 0.f, s1 = 0.f, s2 = 0.f, s3 = 0.f;
    for (int u = lane; u < 512; u += 32) {
        float4 wv = w[u];
        float4 a = hs[u];
        float4 b = hs[512 + u];
        float4 c = hs[1024 + u];
        float4 d = hs[1536 + u];
        s0 += wv.x * a.x + wv.y * a.y + wv.z * a.z + wv.w * a.w;
        s1 += wv.x * b.x + wv.y * b.y + wv.z * b.z + wv.w * b.w;
        s2 += wv.x * c.x + wv.y * c.y + wv.z * c.z + wv.w * c.w;
        s3 += wv.x * d.x + wv.y * d.y + wv.z * d.z + wv.w * d.w;
    }
#pragma unroll
    for (int off = 16; off; off >>= 1) {
        s0 += __shfl_down_sync(0xffffffffu, s0, off);
        s1 += __shfl_down_sync(0xffffffffu, s1, off);
        s2 += __shfl_down_sync(0xffffffffu, s2, off);
        s3 += __shfl_down_sync(0xffffffffu, s3, off);
    }
    if (lane == 0) {
        g_gates[0 * GATE + j] = s0 + g_G0[(size_t)(t * 4 + 0) * GATE + j];
        g_gates[1 * GATE + j] = s1 + g_G0[(size_t)(t * 4 + 1) * GATE + j];
        g_gates[2 * GATE + j] = s2 + g_G0[(size_t)(t * 4 + 2) * GATE + j];
        g_gates[3 * GATE + j] = s3 + g_G0[(size_t)(t * 4 + 3) * GATE + j];
    }
}

__global__ void lstm_update_k(const float* __restrict__ done, int t)
{
    int idx = blockIdx.x * 256 + threadIdx.x;
    if (idx >= BATCH * HID) return;
    int b = idx >> 11, k = idx & 2047;
    float gi = g_gates[b * GATE + k];
    float gf = g_gates[b * GATE + 2048 + k];
    float gg = g_gates[b * GATE + 4096 + k];
    float go = g_gates[b * GATE + 6144 + k];
    float i_ = 1.f / (1.f + expf(-gi));
    float f_ = 1.f / (1.f + expf(-gf));
    float g_ = tanhf(gg);
    float o_ = 1.f / (1.f + expf(-go));
    float m  = 1.f - done[t * 4 + b];
    float c  = f_ * (g_c[idx] * m) + i_ * g_;
    g_c[idx] = c;
    float h  = o_ * tanhf(c);
    g_h[idx] = h;
    g_hid[(size_t)(t * 4 + b) * HID + k] = h;
}

// warp-per-output gemv for tiny heads. out[n*Nout + o] = dot(A[n*lda .. +K], W[o]) + bias[o]
__global__ void gemv_k(const float* __restrict__ A, int lda,
                       const float* __restrict__ W,
                       const float* __restrict__ bias, float* __restrict__ out,
                       int Nout, int K)
{
    int gid = blockIdx.x * 8 + (threadIdx.x >> 5);
    if (gid >= NIMG * Nout) return;
    int lane = threadIdx.x & 31;
    int n = gid / Nout, o = gid - n * Nout;
    const float4* a = (const float4*)(A + (size_t)n * lda);
    const float4* w = (const float4*)(W + (size_t)o * K);
    int K4 = K >> 2;
    float s = 0.f;
    for (int u = lane; u < K4; u += 32) {
        float4 av = a[u], wv = w[u];
        s += av.x * wv.x + av.y * wv.y + av.z * wv.z + av.w * wv.w;
    }
#pragma unroll
    for (int off = 16; off; off >>= 1) s += __shfl_down_sync(0xffffffffu, s, off);
    if (lane == 0) out[(size_t)n * Nout + o] = s + bias[o];
}

__global__ void out_hc_k(float* __restrict__ out)
{
    int i = blockIdx.x * 256 + threadIdx.x;
    if (i < BATCH * HID) {
        out[4736 + i]  = g_h[i];
        out[12928 + i] = g_c[i];
    }
}

// ===================== host orchestration =====================
static void run_gemm2(const float* A, const float* A2, int lda,
                      const float* B, const float* B2adj, int ldb,
                      float* Cfinal, float* part,
                      int M, int N, int K, int S,
                      const float* bias, const float* bias2adj, int xHalf,
                      int act, int colSplit)
{
    dim3 grid(N / 128, M / 128, S);
    if (S == 1) {
        tgemm_k<<<grid, 256>>>(A, B, Cfinal, M, N, K, lda, ldb, K, 1, bias, act,
                               A2, B2adj, bias2adj, xHalf);
    } else {
        tgemm_k<<<grid, 256>>>(A, B, part, M, N, K, lda, ldb, K / S, S, nullptr, 0,
                               A2, B2adj, nullptr, xHalf);
        int MN = M * N;
        reduce_k<<<(MN + 255) / 256, 256>>>(part, Cfinal, MN, N, S, bias, act,
                                            bias2adj ? bias2adj + colSplit : nullptr, colSplit);
    }
}

static void run_gemm(const float* A, const float* B, float* Cfinal, float* part,
                     int M, int N, int K, int S, const float* bias, int act)
{
    run_gemm2(A, nullptr, K, B, nullptr, K, Cfinal, part, M, N, K, S,
              bias, nullptr, 1 << 30, act, 0);
}

extern "C" void kernel_launch(void* const* d_in, const int* in_sizes, int n_in,
                              void* d_out, int out_size)
{
    (void)in_sizes; (void)n_in; (void)out_size;
    const float* x        = (const float*)d_in[0];
    const float* done     = (const float*)d_in[1];
    const float* h0       = (const float*)d_in[2];
    const float* c0       = (const float*)d_in[3];
    const float* conv1_w  = (const float*)d_in[4];
    const float* conv1_b  = (const float*)d_in[5];
    const float* conv2_w  = (const float*)d_in[6];
    const float* conv2_b  = (const float*)d_in[7];
    const float* conv3_w  = (const float*)d_in[8];
    const float* conv3_b  = (const float*)d_in[9];
    const float* fc1_w    = (const float*)d_in[10];
    const float* fc1_b    = (const float*)d_in[11];
    const float* fc2_w    = (const float*)d_in[12];
    const float* fc2_b    = (const float*)d_in[13];
    const float* lstm_wih = (const float*)d_in[14];
    const float* lstm_whh = (const float*)d_in[15];
    const float* lstm_bih = (const float*)d_in[16];
    const float* lstm_bhh = (const float*)d_in[17];
    const float* a1_w = (const float*)d_in[18];
    const float* a1_b = (const float*)d_in[19];
    const float* a2_w = (const float*)d_in[20];
    const float* a2_b = (const float*)d_in[21];
    const float* a3_w = (const float*)d_in[22];
    const float* a3_b = (const float*)d_in[23];
    const float* v1_w = (const float*)d_in[24];
    const float* v1_b = (const float*)d_in[25];
    const float* v2_w = (const float*)d_in[26];
    const float* v2_b = (const float*)d_in[27];
    const float* v3_w = (const float*)d_in[28];
    const float* v3_b = (const float*)d_in[29];
    float* out = (float*)d_out;

    float *A1, *C1, *A2, *C2, *A3, *C3, *F, *H1, *H2, *G0, *cb, *b1, *b2, *hid, *part;
    float *w2t, *w3t;
    cudaGetSymbolAddress((void**)&A1, g_A1);
    cudaGetSymbolAddress((void**)&C1, g_C1);
    cudaGetSymbolAddress((void**)&A2, g_A2);
    cudaGetSymbolAddress((void**)&C2, g_C2);
    cudaGetSymbolAddress((void**)&A3, g_A3);
    cudaGetSymbolAddress((void**)&C3, g_C3);
    cudaGetSymbolAddress((void**)&F,  g_F);
    cudaGetSymbolAddress((void**)&H1, g_H1);
    cudaGetSymbolAddress((void**)&H2, g_H2);
    cudaGetSymbolAddress((void**)&G0, g_G0);
    cudaGetSymbolAddress((void**)&cb, g_cb);
    cudaGetSymbolAddress((void**)&b1, g_b1);
    cudaGetSymbolAddress((void**)&b2, g_b2);
    cudaGetSymbolAddress((void**)&w2t, g_w2t);
    cudaGetSymbolAddress((void**)&w3t, g_w3t);
    cudaGetSymbolAddress((void**)&hid, g_hid);
    cudaGetSymbolAddress((void**)&part, g_part);

    // --- conv backbone ---
    im2col1_k<<<(C1_POS * 64 + 255) / 256, 256>>>(x);
    run_gemm(A1, conv1_w, C1, part, C1_POS, C1_OC, 64, 1, nullptr, 0);
    pool1_k<<<(NIMG * P1_H * P1_W * 256 + 255) / 256, 256>>>(conv1_b);

    w2t_k<<<(128 * 16 * 256 + 255) / 256, 256>>>(conv2_w);
    im2col2_k<<<(C2_POS * 4096 + 255) / 256, 256>>>();
    run_gemm(A2, w2t, C2, part, C2_POS, 128, 4096, 4, conv2_b, 1);

    w3t_k<<<(128 * 4 * 128 + 255) / 256, 256>>>(conv3_w);
    im2col3_k<<<(C3_POS * 512 + 255) / 256, 256>>>();
    run_gemm(A3, w3t, C3, part, C3_POS, 128, 512, 2, conv3_b, 1);

    flatten_k<<<(NIMG * FC1_K + 255) / 256, 256>>>();

    // --- MLP ---
    run_gemm(F,  fc1_w, H1, part, NIMG, 4096, FC1_K, 8, fc1_b, 1);
    run_gemm(H1, fc2_w, H2, part, NIMG, 4096, 4096, 8, fc2_b, 1);

    // --- LSTM input projection for all T at once ---
    cbias_k<<<(GATE + 255) / 256, 256>>>(lstm_bih, lstm_bhh);
    run_gemm(H2, lstm_wih, G0, part, NIMG, GATE, 4096, 4, cb, 0);

    // --- recurrence ---
    init_hc_k<<<(BATCH * HID + 255) / 256, 256>>>(h0, c0);
    for (int t = 0; t < TSTEPS; t++) {
        lstm_gates_k<<<GATE / 8, 256>>>(lstm_whh, done, t);
        lstm_update_k<<<(BATCH * HID + 255) / 256, 256>>>(done, t);
    }

    // --- merged actor|critic heads ---
    // layer1: C[128,2048] = hid @ [a1_w | v1_w]^T ; cols 0-1023 actor, 1024-2047 critic
    {
        const int xHalf = 8;  // 1024 / 128
        const float* v1w_adj = v1_w - (size_t)xHalf * 128 * 2048;
        const float* v1b_adj = v1_b - 1024;
        run_gemm2(hid, nullptr, 2048, a1_w, v1w_adj, 2048, b1, part,
                  NIMG, 2048, 2048, 16, a1_b, v1b_adj, xHalf, 1, 1024);
    }
    // layer2: C[128,1024] = [b1[:, :1024] @ a2_w^T | b1[:, 1024:] @ v2_w^T]
    {
        const int xHalf = 4;  // 512 / 128
        const float* v2w_adj = v2_w - (size_t)xHalf * 128 * 1024;
        const float* v2b_adj = v2_b - 512;
        run_gemm2(b1, b1 + 1024, 2048, a2_w, v2w_adj, 1024, b2, part,
                  NIMG, 1024, 1024, 16, a2_b, v2b_adj, xHalf, 1, 512);
    }
    gemv_k<<<(NIMG * 36 + 7) / 8, 256>>>(b2, 1024, a3_w, a3_b, out, 36, 512);
    gemv_k<<<(NIMG * 1 + 7) / 8, 256>>>(b2 + 512, 1024, v3_w, v3_b, out + 4608, 1, 512);

    // --- hn, cn ---
    out_hc_k<<<(BATCH * HID + 255) / 256, 256>>>(out);
}

// round 12
// speedup vs baseline: 1.2217x; 1.2217x over previous
#include <cuda_runtime.h>
#include <math.h>
#include <stdint.h>

// ===================== dims =====================
enum : int {
    NIMG = 128, IMG_H = 72, IMG_W = 128,
    C1_OC = 256, C1_H = 33, C1_W = 61, C1_POS = NIMG * C1_H * C1_W,   // 257664
    P1_H = 15, P1_W = 29,
    C2_OC = 128, C2_H = 6, C2_W = 13, C2_POS = NIMG * C2_H * C2_W,    // 9984
    C3_OC = 128, C3_H = 5, C3_W = 12, C3_POS = NIMG * C3_H * C3_W,    // 7680
    FC1_N = 4096, FC1_K = 7680,
    HID = 2048, GATE = 8192,
    TSTEPS = 32, BATCH = 4,
};

// ===================== scratch (device globals; allocation-free) =====================
__device__ __align__(16) float g_A1[C1_POS * 64];                 // im2col conv1
__device__ __align__(16) float g_C1[(size_t)C1_POS * C1_OC];      // conv1 out [pos][oc]
__device__ __align__(16) float g_P1[NIMG * P1_H * P1_W * 256];    // pooled NHWC
__device__ __align__(16) float g_A2[(size_t)C2_POS * 4096];       // im2col conv2
__device__ __align__(16) float g_C2[C2_POS * 128];
__device__ __align__(16) float g_A3[C3_POS * 512];
__device__ __align__(16) float g_C3[C3_POS * 128];
__device__ __align__(16) float g_F [NIMG * FC1_K];
__device__ __align__(16) float g_H1[NIMG * 4096];
__device__ __align__(16) float g_H2[NIMG * 4096];
__device__ __align__(16) float g_G0[NIMG * GATE];
__device__ __align__(16) float g_h[BATCH * HID];
__device__ __align__(16) float g_c[BATCH * HID];
__device__ __align__(16) float g_hid[NIMG * HID];
__device__ __align__(16) float g_b1[NIMG * 2048];                 // merged actor|critic layer1
__device__ __align__(16) float g_b2[NIMG * 1024];                 // merged actor|critic layer2
__device__ __align__(16) float g_w2t[128 * 16 * 256];             // conv2_w -> [oc][pq][c]
__device__ __align__(16) float g_w3t[128 * 4 * 128];              // conv3_w -> [oc][pq][c]
__device__ __align__(16) float g_cb[GATE];                        // bih + bhh
__device__ __align__(16) float g_part[(size_t)4 * C2_POS * 128];  // split-K partials (max case)

__device__ __forceinline__ float leakyf(float z) { return z > 0.f ? z : 0.01f * z; }
__device__ __forceinline__ uint32_t f2tf(float x) {
    uint32_t r; asm("cvt.rna.tf32.f32 %0, %1;" : "=r"(r) : "f"(x)); return r;
}
__device__ __forceinline__ void split_tf32(float v, uint32_t& hi, uint32_t& lo) {
    hi = f2tf(v);
    lo = f2tf(v - __uint_as_float(hi));
}
__device__ __forceinline__ void mma_tf32(float& c0, float& c1, float& c2, float& c3,
                                         uint32_t a0, uint32_t a1, uint32_t a2, uint32_t a3,
                                         uint32_t b0, uint32_t b1)
{
    asm volatile("mma.sync.aligned.m16n8k8.row.col.f32.tf32.tf32.f32 "
                 "{%0,%1,%2,%3}, {%4,%5,%6,%7}, {%8,%9}, {%0,%1,%2,%3};"
                 : "+f"(c0), "+f"(c1), "+f"(c2), "+f"(c3)
                 : "r"(a0), "r"(a1), "r"(a2), "r"(a3), "r"(b0), "r"(b1));
}

// ===================== 3xTF32 tensor-core GEMM: C[M,N] = A[M,K] * B[N,K]^T =====================
// CTA tile 128x128 (8 warps, 2x4), warp tile 64x32 (4x4 m16n8k8 frags), k-chunk 16.
// hi/lo tf32 split; acc += a_hi*b_hi + a_hi*b_lo + a_lo*b_hi (~22-bit effective mantissa).
// Double-buffered smem (2 stages x 40KB, dynamic): store(buf); sync; prefetch; mma(buf).
// Scalar [row][20] smem layout: frag-load banks (20g+tg) mod 32 cover all 32 -> conflict-free.
// lda/ldb = row strides (>= K). Dual-operand: blocks with blockIdx.x >= xHalf use
// A2/B2/bias2 (pre-adjusted by caller so global indexing works).
// Split-K: blockIdx.z = chunk; writes raw partial at C + z*M*N when nSplit>1.
__global__ void __launch_bounds__(256, 2) tgemm_k(
    const float* __restrict__ A, const float* __restrict__ B, float* __restrict__ C,
    int M, int N, int K, int lda, int ldb, int Kc, int nSplit,
    const float* __restrict__ bias, int act,
    const float* __restrict__ A2, const float* __restrict__ B2,
    const float* __restrict__ bias2, int xHalf)
{
    extern __shared__ uint32_t dsm[];   // 2 stages x 4 arrays x 128*20 words = 81920 B
    const int STG = 10240;              // words per stage

    const int s = blockIdx.z;
    const int tid = threadIdx.x;
    const int warp = tid >> 5, lane = tid & 31;
    const int g = lane >> 2, tg = lane & 3;
    const int wm = (warp >> 2) * 64;
    const int wn = (warp & 3) * 32;

    const int sm = tid >> 1;                    // staging row 0..127
    const int sk = (tid & 1) * 8;               // staging k offset 0 or 8

    const float* Abase = (A2 && blockIdx.x >= xHalf) ? A2 : A;
    const float* Bbase = (B2 && blockIdx.x >= xHalf) ? B2 : B;
    const float* biasUse = (bias2 && blockIdx.x >= xHalf) ? bias2 : bias;

    const float* Ap = Abase + (size_t)s * Kc + (size_t)(blockIdx.y * 128 + sm) * lda + sk;
    const float* Bp = Bbase + (size_t)s * Kc + (size_t)(blockIdx.x * 128 + sm) * ldb + sk;

    float acc[4][4][4];
#pragma unroll
    for (int i = 0; i < 4; i++)
#pragma unroll
        for (int j = 0; j < 4; j++)
#pragma unroll
            for (int r = 0; r < 4; r++) acc[i][j][r] = 0.f;

    // preload stage 0
    float4 va0 = *(const float4*)(Ap);
    float4 va1 = *(const float4*)(Ap + 4);
    float4 vb0 = *(const float4*)(Bp);
    float4 vb1 = *(const float4*)(Bp + 4);

    int buf = 0;
    for (int k0 = 0; k0 < Kc; k0 += 16, buf ^= 1) {
        uint32_t* sAh = dsm + buf * STG;
        uint32_t* sAl = sAh + 2560;
        uint32_t* sBh = sAh + 5120;
        uint32_t* sBl = sAh + 7680;

        // split + store current chunk into stage `buf`
        {
            uint32_t h0, h1, h2, h3, l0, l1, l2, l3;
            split_tf32(va0.x, h0, l0); split_tf32(va0.y, h1, l1);
            split_tf32(va0.z, h2, l2); split_tf32(va0.w, h3, l3);
            *(uint4*)&sAh[sm * 20 + sk] = make_uint4(h0, h1, h2, h3);
            *(uint4*)&sAl[sm * 20 + sk] = make_uint4(l0, l1, l2, l3);
            split_tf32(va1.x, h0, l0); split_tf32(va1.y, h1, l1);
            split_tf32(va1.z, h2, l2); split_tf32(va1.w, h3, l3);
            *(uint4*)&sAh[sm * 20 + sk + 4] = make_uint4(h0, h1, h2, h3);
            *(uint4*)&sAl[sm * 20 + sk + 4] = make_uint4(l0, l1, l2, l3);
            split_tf32(vb0.x, h0, l0); split_tf32(vb0.y, h1, l1);
            split_tf32(vb0.z, h2, l2); split_tf32(vb0.w, h3, l3);
            *(uint4*)&sBh[sm * 20 + sk] = make_uint4(h0, h1, h2, h3);
            *(uint4*)&sBl[sm * 20 + sk] = make_uint4(l0, l1, l2, l3);
            split_tf32(vb1.x, h0, l0); split_tf32(vb1.y, h1, l1);
            split_tf32(vb1.z, h2, l2); split_tf32(vb1.w, h3, l3);
            *(uint4*)&sBh[sm * 20 + sk + 4] = make_uint4(h0, h1, h2, h3);
            *(uint4*)&sBl[sm * 20 + sk + 4] = make_uint4(l0, l1, l2, l3);
        }
        __syncthreads();   // single barrier per chunk (WAR to this buf is 2 iters away)

        if (k0 + 16 < Kc) {   // prefetch next chunk, overlapped with mma below
            va0 = *(const float4*)(Ap + k0 + 16);
            va1 = *(const float4*)(Ap + k0 + 20);
            vb0 = *(const float4*)(Bp + k0 + 16);
            vb1 = *(const float4*)(Bp + k0 + 20);
        }

#pragma unroll
        for (int ko = 0; ko < 16; ko += 8) {
            uint32_t af[4][4], bf[4][2];
            // ---- pass 1: a_hi * b_hi ----
#pragma unroll
            for (int mf = 0; mf < 4; mf++) {
                int r0 = (wm + mf * 16 + g) * 20;
                af[mf][0] = sAh[r0 + ko + tg];
                af[mf][1] = sAh[r0 + 160 + ko + tg];
                af[mf][2] = sAh[r0 + ko + tg + 4];
                af[mf][3] = sAh[r0 + 160 + ko + tg + 4];
            }
#pragma unroll
            for (int nf = 0; nf < 4; nf++) {
                int n0 = (wn + nf * 8 + g) * 20;
                bf[nf][0] = sBh[n0 + ko + tg];
                bf[nf][1] = sBh[n0 + ko + tg + 4];
            }
#pragma unroll
            for (int mf = 0; mf < 4; mf++)
#pragma unroll
                for (int nf = 0; nf < 4; nf++)
                    mma_tf32(acc[mf][nf][0], acc[mf][nf][1], acc[mf][nf][2], acc[mf][nf][3],
                             af[mf][0], af[mf][1], af[mf][2], af[mf][3],
                             bf[nf][0], bf[nf][1]);
            // ---- pass 2: a_hi * b_lo ----
#pragma unroll
            for (int nf = 0; nf < 4; nf++) {
                int n0 = (wn + nf * 8 + g) * 20;
                bf[nf][0] = sBl[n0 + ko + tg];
                bf[nf][1] = sBl[n0 + ko + tg + 4];
            }
#pragma unroll
            for (int mf = 0; mf < 4; mf++)
#pragma unroll
                for (int nf = 0; nf < 4; nf++)
                    mma_tf32(acc[mf][nf][0], acc[mf][nf][1], acc[mf][nf][2], acc[mf][nf][3],
                             af[mf][0], af[mf][1], af[mf][2], af[mf][3],
                             bf[nf][0], bf[nf][1]);
            // ---- pass 3: a_lo * b_hi ----
#pragma unroll
            for (int mf = 0; mf < 4; mf++) {
                int r0 = (wm + mf * 16 + g) * 20;
                af[mf][0] = sAl[r0 + ko + tg];
                af[mf][1] = sAl[r0 + 160 + ko + tg];
                af[mf][2] = sAl[r0 + ko + tg + 4];
                af[mf][3] = sAl[r0 + 160 + ko + tg + 4];
            }
#pragma unroll
            for (int nf = 0; nf < 4; nf++) {
                int n0 = (wn + nf * 8 + g) * 20;
                bf[nf][0] = sBh[n0 + ko + tg];
                bf[nf][1] = sBh[n0 + ko + tg + 4];
            }
#pragma unroll
            for (int mf = 0; mf < 4; mf++)
#pragma unroll
                for (int nf = 0; nf < 4; nf++)
                    mma_tf32(acc[mf][nf][0], acc[mf][nf][1], acc[mf][nf][2], acc[mf][nf][3],
                             af[mf][0], af[mf][1], af[mf][2], af[mf][3],
                             bf[nf][0], bf[nf][1]);
        }
    }

    // epilogue
    const int rowBase = blockIdx.y * 128 + wm + g;
    const int colBase = blockIdx.x * 128 + wn + tg * 2;
    if (nSplit > 1) {
        float* Cp = C + (size_t)s * M * N;
#pragma unroll
        for (int mf = 0; mf < 4; mf++)
#pragma unroll
            for (int nf = 0; nf < 4; nf++) {
                int row = rowBase + mf * 16;
                int col = colBase + nf * 8;
                *(float2*)&Cp[(size_t)row * N + col]       = make_float2(acc[mf][nf][0], acc[mf][nf][1]);
                *(float2*)&Cp[(size_t)(row + 8) * N + col] = make_float2(acc[mf][nf][2], acc[mf][nf][3]);
            }
    } else {
#pragma unroll
        for (int mf = 0; mf < 4; mf++)
#pragma unroll
            for (int nf = 0; nf < 4; nf++) {
                int row = rowBase + mf * 16;
                int col = colBase + nf * 8;
                float v0 = acc[mf][nf][0], v1 = acc[mf][nf][1];
                float v2 = acc[mf][nf][2], v3 = acc[mf][nf][3];
                if (biasUse) {
                    float b0 = biasUse[col], b1 = biasUse[col + 1];
                    v0 += b0; v1 += b1; v2 += b0; v3 += b1;
                }
                if (act) { v0 = leakyf(v0); v1 = leakyf(v1); v2 = leakyf(v2); v3 = leakyf(v3); }
                *(float2*)&C[(size_t)row * N + col]       = make_float2(v0, v1);
                *(float2*)&C[(size_t)(row + 8) * N + col] = make_float2(v2, v3);
            }
    }
}

__global__ void reduce_k(const float* __restrict__ P, float* __restrict__ C,
                         int MN, int N, int S, const float* __restrict__ bias, int act,
                         const float* __restrict__ bias2, int colSplit)
{
    int idx = blockIdx.x * 256 + threadIdx.x;
    if (idx >= MN) return;
    float v = 0.f;
    for (int s = 0; s < S; s++) v += P[(size_t)s * MN + idx];
    int col = idx % N;
    if (bias2 && col >= colSplit) v += bias2[col - colSplit];
    else if (bias) v += bias[col];
    if (act) v = leakyf(v);
    C[idx] = v;
}

// ===================== layer-specific kernels =====================
__global__ void im2col1_k(const float* __restrict__ x)
{
    int idx = blockIdx.x * 256 + threadIdx.x;
    if (idx >= C1_POS * 64) return;
    int k = idx & 63, pos = idx >> 6;
    int j = pos % C1_W, t = pos / C1_W;
    int i = t % C1_H, n = t / C1_H;
    int p = k >> 3, q = k & 7;
    g_A1[idx] = x[((size_t)n * IMG_H + (2 * i + p)) * IMG_W + (2 * j + q)] * (1.f / 255.f);
}

__global__ void pool1_k(const float* __restrict__ conv1_b)
{
    int idx = blockIdx.x * 256 + threadIdx.x;                 // NHWC output
    if (idx >= NIMG * P1_H * P1_W * 256) return;
    int c = idx & 255, r = idx >> 8;
    int x = r % P1_W; r /= P1_W;
    int y = r % P1_H; int n = r / P1_H;
    float m = -3.4e38f;
#pragma unroll
    for (int p = 0; p < 4; p++)
#pragma unroll
        for (int q = 0; q < 4; q++) {
            int pos = (n * C1_H + 2 * y + p) * C1_W + (2 * x + q);
            float v = g_C1[(size_t)pos * 256 + c];
            m = fmaxf(m, v);
        }
    g_P1[idx] = leakyf(m + conv1_b[c]);
}

// merged prep: w2 transpose + w3 transpose + combined lstm bias
__global__ void prep_k(const float* __restrict__ w2, const float* __restrict__ w3,
                       const float* __restrict__ bih, const float* __restrict__ bhh)
{
    int idx = blockIdx.x * 256 + threadIdx.x;
    if (idx < 128 * 16 * 256) {   // w2t: [oc][c][pq] -> [oc][pq][c]
        int c = idx & 255, r = idx >> 8;
        int pq = r & 15, oc = r >> 4;
        g_w2t[idx] = w2[((size_t)oc * 256 + c) * 16 + pq];
    }
    if (idx < 128 * 4 * 128) {    // w3t
        int c = idx & 127, r = idx >> 7;
        int pq = r & 3, oc = r >> 2;
        g_w3t[idx] = w3[((size_t)oc * 128 + c) * 4 + pq];
    }
    if (idx < GATE) g_cb[idx] = bih[idx] + bhh[idx];
}

__global__ void im2col2_k()
{
    int idx = blockIdx.x * 256 + threadIdx.x;
    if (idx >= C2_POS * 4096) return;
    int c = idx & 255, r = idx >> 8;
    int pq = r & 15, pos2 = r >> 4;
    int p = pq >> 2, q = pq & 3;
    int n = pos2 / (C2_H * C2_W), rem = pos2 % (C2_H * C2_W);
    int i = rem / C2_W, j = rem % C2_W;
    g_A2[idx] = g_P1[(((size_t)n * P1_H + (2 * i + p)) * P1_W + (2 * j + q)) * 256 + c];
}

__global__ void im2col3_k()
{
    int idx = blockIdx.x * 256 + threadIdx.x;
    if (idx >= C3_POS * 512) return;
    int c = idx & 127, r = idx >> 7;
    int pq = r & 3, pos3 = r >> 2;
    int p = pq >> 1, q = pq & 1;
    int n = pos3 / (C3_H * C3_W), rem = pos3 % (C3_H * C3_W);
    int i = rem / C3_W, j = rem % C3_W;
    g_A3[idx] = g_C2[((size_t)(n * C2_H + i + p) * C2_W + (j + q)) * 128 + c];
}

__global__ void flatten_k() // [pos][c] -> [n][c*60 + i*12 + j]
{
    int idx = blockIdx.x * 256 + threadIdx.x;
    if (idx >= NIMG * FC1_K) return;
    int n = idx / FC1_K, r = idx % FC1_K;
    int c = r / 60, t = r % 60;
    int i = t / 12, j = t % 12;
    g_F[idx] = g_C3[(size_t)((n * C3_H + i) * C3_W + j) * 128 + c];
}

__global__ void init_hc_k(const float* __restrict__ h0, const float* __restrict__ c0)
{
    int i = blockIdx.x * 256 + threadIdx.x;
    if (i < BATCH * HID) { g_h[i] = h0[i]; g_c[i] = c0[i]; }
}

// ===== fused LSTM step: warp per hidden unit k; computes all 4 gates x 4 batches,
// applies the cell update inline, writes h straight into g_hid[t] (next step reads
// h from g_hid[t-1], so no cross-block h race). grid = HID/8 = 256 blocks.
__global__ void __launch_bounds__(256) lstm_step_k(const float* __restrict__ whh,
                                                   const float* __restrict__ done,
                                                   const float* __restrict__ hprev,
                                                   int t)
{
    __shared__ float4 hs[BATCH * 512];
    int tid = threadIdx.x;
    float m0 = 1.f - done[t * 4 + 0];
    float m1 = 1.f - done[t * 4 + 1];
    float m2 = 1.f - done[t * 4 + 2];
    float m3 = 1.f - done[t * 4 + 3];
    const float4* h4 = (const float4*)hprev;
    for (int u = tid; u < BATCH * 512; u += 256) {
        int b = u >> 9;
        float mb = (b == 0) ? m0 : (b == 1) ? m1 : (b == 2) ? m2 : m3;
        float4 v = h4[u];
        v.x *= mb; v.y *= mb; v.z *= mb; v.w *= mb;
        hs[u] = v;
    }
    __syncthreads();

    int warp = tid >> 5, lane = tid & 31;
    int k = blockIdx.x * 8 + warp;                  // hidden unit
    const float4* w0 = (const float4*)(whh + (size_t)(k         ) * HID);
    const float4* w1 = (const float4*)(whh + (size_t)(k + 1*HID ) * HID);
    const float4* w2 = (const float4*)(whh + (size_t)(k + 2*HID ) * HID);
    const float4* w3 = (const float4*)(whh + (size_t)(k + 3*HID ) * HID);

    float sv[16];                                   // [gate][batch]
#pragma unroll
    for (int i = 0; i < 16; i++) sv[i] = 0.f;

    for (int u = lane; u < 512; u += 32) {
        float4 a = hs[u], b = hs[512 + u], c = hs[1024 + u], d = hs[1536 + u];
        float4 w;
        w = w0[u];
        sv[0]  += w.x * a.x + w.y * a.y + w.z * a.z + w.w * a.w;
        sv[1]  += w.x * b.x + w.y * b.y + w.z * b.z + w.w * b.w;
        sv[2]  += w.x * c.x + w.y * c.y + w.z * c.z + w.w * c.w;
        sv[3]  += w.x * d.x + w.y * d.y + w.z * d.z + w.w * d.w;
        w = w1[u];
        sv[4]  += w.x * a.x + w.y * a.y + w.z * a.z + w.w * a.w;
        sv[5]  += w.x * b.x + w.y * b.y + w.z * b.z + w.w * b.w;
        sv[6]  += w.x * c.x + w.y * c.y + w.z * c.z + w.w * c.w;
        sv[7]  += w.x * d.x + w.y * d.y + w.z * d.z + w.w * d.w;
        w = w2[u];
        sv[8]  += w.x * a.x + w.y * a.y + w.z * a.z + w.w * a.w;
        sv[9]  += w.x * b.x + w.y * b.y + w.z * b.z + w.w * b.w;
        sv[10] += w.x * c.x + w.y * c.y + w.z * c.z + w.w * c.w;
        sv[11] += w.x * d.x + w.y * d.y + w.z * d.z + w.w * d.w;
        w = w3[u];
        sv[12] += w.x * a.x + w.y * a.y + w.z * a.z + w.w * a.w;
        sv[13] += w.x * b.x + w.y * b.y + w.z * b.z + w.w * b.w;
        sv[14] += w.x * c.x + w.y * c.y + w.z * c.z + w.w * c.w;
        sv[15] += w.x * d.x + w.y * d.y + w.z * d.z + w.w * d.w;
    }
#pragma unroll
    for (int i = 0; i < 16; i++) {
#pragma unroll
        for (int off = 16; off; off >>= 1)
            sv[i] += __shfl_down_sync(0xffffffffu, sv[i], off);
    }

    if (lane == 0) {
        const float mm[4] = { m0, m1, m2, m3 };
#pragma unroll
        for (int b = 0; b < 4; b++) {
            const float* G0r = g_G0 + (size_t)(t * 4 + b) * GATE;
            float gi = sv[0 + b]  + G0r[k];
            float gf = sv[4 + b]  + G0r[k + 2048];
            float gg = sv[8 + b]  + G0r[k + 4096];
            float go = sv[12 + b] + G0r[k + 6144];
            float i_ = 1.f / (1.f + expf(-gi));
            float f_ = 1.f / (1.f + expf(-gf));
            float g_ = tanhf(gg);
            float o_ = 1.f / (1.f + expf(-go));
            int idx = b * HID + k;
            float c = f_ * (g_c[idx] * mm[b]) + i_ * g_;
            g_c[idx] = c;
            g_hid[(size_t)(t * 4 + b) * HID + k] = o_ * tanhf(c);
        }
    }
}

// warp-per-output gemv for tiny heads. out[n*Nout + o] = dot(A[n*lda .. +K], W[o]) + bias[o]
__global__ void gemv_k(const float* __restrict__ A, int lda,
                       const float* __restrict__ W,
                       const float* __restrict__ bias, float* __restrict__ out,
                       int Nout, int K)
{
    int gid = blockIdx.x * 8 + (threadIdx.x >> 5);
    if (gid >= NIMG * Nout) return;
    int lane = threadIdx.x & 31;
    int n = gid / Nout, o = gid - n * Nout;
    const float4* a = (const float4*)(A + (size_t)n * lda);
    const float4* w = (const float4*)(W + (size_t)o * K);
    int K4 = K >> 2;
    float s = 0.f;
    for (int u = lane; u < K4; u += 32) {
        float4 av = a[u], wv = w[u];
        s += av.x * wv.x + av.y * wv.y + av.z * wv.z + av.w * wv.w;
    }
#pragma unroll
    for (int off = 16; off; off >>= 1) s += __shfl_down_sync(0xffffffffu, s, off);
    if (lane == 0) out[(size_t)n * Nout + o] = s + bias[o];
}

__global__ void out_hc_k(float* __restrict__ out)
{
    int i = blockIdx.x * 256 + threadIdx.x;
    if (i < BATCH * HID) {
        out[4736 + i]  = g_hid[(size_t)(TSTEPS - 1) * 4 * HID + i];   // hn = outs[-1]
        out[12928 + i] = g_c[i];
    }
}

// ===================== host orchestration =====================
enum : int { TGEMM_SMEM = 81920 };

static void run_gemm2(const float* A, const float* A2, int lda,
                      const float* B, const float* B2adj, int ldb,
                      float* Cfinal, float* part,
                      int M, int N, int K, int S,
                      const float* bias, const float* bias2adj, int xHalf,
                      int act, int colSplit)
{
    dim3 grid(N / 128, M / 128, S);
    if (S == 1) {
        tgemm_k<<<grid, 256, TGEMM_SMEM>>>(A, B, Cfinal, M, N, K, lda, ldb, K, 1, bias, act,
                                           A2, B2adj, bias2adj, xHalf);
    } else {
        tgemm_k<<<grid, 256, TGEMM_SMEM>>>(A, B, part, M, N, K, lda, ldb, K / S, S, nullptr, 0,
                                           A2, B2adj, nullptr, xHalf);
        int MN = M * N;
        reduce_k<<<(MN + 255) / 256, 256>>>(part, Cfinal, MN, N, S, bias, act,
                                            bias2adj ? bias2adj + colSplit : nullptr, colSplit);
    }
}

static void run_gemm(const float* A, const float* B, float* Cfinal, float* part,
                     int M, int N, int K, int S, const float* bias, int act)
{
    run_gemm2(A, nullptr, K, B, nullptr, K, Cfinal, part, M, N, K, S,
              bias, nullptr, 1 << 30, act, 0);
}

extern "C" void kernel_launch(void* const* d_in, const int* in_sizes, int n_in,
                              void* d_out, int out_size)
{
    (void)in_sizes; (void)n_in; (void)out_size;
    const float* x        = (const float*)d_in[0];
    const float* done     = (const float*)d_in[1];
    const float* h0       = (const float*)d_in[2];
    const float* c0       = (const float*)d_in[3];
    const float* conv1_w  = (const float*)d_in[4];
    const float* conv1_b  = (const float*)d_in[5];
    const float* conv2_w  = (const float*)d_in[6];
    const float* conv2_b  = (const float*)d_in[7];
    const float* conv3_w  = (const float*)d_in[8];
    const float* conv3_b  = (const float*)d_in[9];
    const float* fc1_w    = (const float*)d_in[10];
    const float* fc1_b    = (const float*)d_in[11];
    const float* fc2_w    = (const float*)d_in[12];
    const float* fc2_b    = (const float*)d_in[13];
    const float* lstm_wih = (const float*)d_in[14];
    const float* lstm_whh = (const float*)d_in[15];
    const float* lstm_bih = (const float*)d_in[16];
    const float* lstm_bhh = (const float*)d_in[17];
    const float* a1_w = (const float*)d_in[18];
    const float* a1_b = (const float*)d_in[19];
    const float* a2_w = (const float*)d_in[20];
    const float* a2_b = (const float*)d_in[21];
    const float* a3_w = (const float*)d_in[22];
    const float* a3_b = (const float*)d_in[23];
    const float* v1_w = (const float*)d_in[24];
    const float* v1_b = (const float*)d_in[25];
    const float* v2_w = (const float*)d_in[26];
    const float* v2_b = (const float*)d_in[27];
    const float* v3_w = (const float*)d_in[28];
    const float* v3_b = (const float*)d_in[29];
    float* out = (float*)d_out;

    static int smemSet = 0;
    if (!smemSet) {
        cudaFuncSetAttribute(tgemm_k, cudaFuncAttributeMaxDynamicSharedMemorySize, TGEMM_SMEM);
        smemSet = 1;
    }

    float *A1, *C1, *A2, *C2, *A3, *C3, *F, *H1, *H2, *G0, *cb, *b1, *b2, *hid, *part, *hbuf;
    float *w2t, *w3t;
    cudaGetSymbolAddress((void**)&A1, g_A1);
    cudaGetSymbolAddress((void**)&C1, g_C1);
    cudaGetSymbolAddress((void**)&A2, g_A2);
    cudaGetSymbolAddress((void**)&C2, g_C2);
    cudaGetSymbolAddress((void**)&A3, g_A3);
    cudaGetSymbolAddress((void**)&C3, g_C3);
    cudaGetSymbolAddress((void**)&F,  g_F);
    cudaGetSymbolAddress((void**)&H1, g_H1);
    cudaGetSymbolAddress((void**)&H2, g_H2);
    cudaGetSymbolAddress((void**)&G0, g_G0);
    cudaGetSymbolAddress((void**)&cb, g_cb);
    cudaGetSymbolAddress((void**)&b1, g_b1);
    cudaGetSymbolAddress((void**)&b2, g_b2);
    cudaGetSymbolAddress((void**)&w2t, g_w2t);
    cudaGetSymbolAddress((void**)&w3t, g_w3t);
    cudaGetSymbolAddress((void**)&hid, g_hid);
    cudaGetSymbolAddress((void**)&part, g_part);
    cudaGetSymbolAddress((void**)&hbuf, g_h);

    // --- conv backbone ---
    im2col1_k<<<(C1_POS * 64 + 255) / 256, 256>>>(x);
    run_gemm(A1, conv1_w, C1, part, C1_POS, C1_OC, 64, 1, nullptr, 0);
    pool1_k<<<(NIMG * P1_H * P1_W * 256 + 255) / 256, 256>>>(conv1_b);

    prep_k<<<(128 * 16 * 256 + 255) / 256, 256>>>(conv2_w, conv3_w, lstm_bih, lstm_bhh);
    im2col2_k<<<(C2_POS * 4096 + 255) / 256, 256>>>();
    run_gemm(A2, w2t, C2, part, C2_POS, 128, 4096, 4, conv2_b, 1);

    im2col3_k<<<(C3_POS * 512 + 255) / 256, 256>>>();
    run_gemm(A3, w3t, C3, part, C3_POS, 128, 512, 2, conv3_b, 1);

    flatten_k<<<(NIMG * FC1_K + 255) / 256, 256>>>();

    // --- MLP ---
    run_gemm(F,  fc1_w, H1, part, NIMG, 4096, FC1_K, 8, fc1_b, 1);
    run_gemm(H1, fc2_w, H2, part, NIMG, 4096, 4096, 8, fc2_b, 1);

    // --- LSTM input projection for all T at once ---
    run_gemm(H2, lstm_wih, G0, part, NIMG, GATE, 4096, 4, cb, 0);

    // --- recurrence (fused gate+update; h ping-pongs through g_hid rows) ---
    init_hc_k<<<(BATCH * HID + 255) / 256, 256>>>(h0, c0);
    for (int t = 0; t < TSTEPS; t++) {
        const float* hprev = (t == 0) ? hbuf : hid + (size_t)(t - 1) * 4 * HID;
        lstm_step_k<<<HID / 8, 256>>>(lstm_whh, done, hprev, t);
    }

    // --- merged actor|critic heads ---
    {
        const int xHalf = 8;  // 1024 / 128
        const float* v1w_adj = v1_w - (size_t)xHalf * 128 * 2048;
        const float* v1b_adj = v1_b - 1024;
        run_gemm2(hid, nullptr, 2048, a1_w, v1w_adj, 2048, b1, part,
                  NIMG, 2048, 2048, 16, a1_b, v1b_adj, xHalf, 1, 1024);
    }
    {
        const int xHalf = 4;  // 512 / 128
        const float* v2w_adj = v2_w - (size_t)xHalf * 128 * 1024;
        const float* v2b_adj = v2_b - 512;
        run_gemm2(b1, b1 + 1024, 2048, a2_w, v2w_adj, 1024, b2, part,
                  NIMG, 1024, 1024, 16, a2_b, v2b_adj, xHalf, 1, 512);
    }
    gemv_k<<<(NIMG * 36 + 7) / 8, 256>>>(b2, 1024, a3_w, a3_b, out, 36, 512);
    gemv_k<<<(NIMG * 1 + 7) / 8, 256>>>(b2 + 512, 1024, v3_w, v3_b, out + 4608, 1, 512);

    // --- hn, cn ---
    out_hc_k<<<(BATCH * HID + 255) / 256, 256>>>(out);
}

// round 15
// speedup vs baseline: 1.4143x; 1.1577x over previous
#include <cuda_runtime.h>
#include <math.h>
#include <stdint.h>

// ===================== dims =====================
enum : int {
    NIMG = 128, IMG_H = 72, IMG_W = 128,
    C1_OC = 256, C1_H = 33, C1_W = 61, C1_POS = NIMG * C1_H * C1_W,   // 257664
    P1_H = 15, P1_W = 29,
    C2_OC = 128, C2_H = 6, C2_W = 13, C2_POS = NIMG * C2_H * C2_W,    // 9984
    C3_OC = 128, C3_H = 5, C3_W = 12, C3_POS = NIMG * C3_H * C3_W,    // 7680
    FC1_N = 4096, FC1_K = 7680,
    HID = 2048, GATE = 8192,
    TSTEPS = 32, BATCH = 4,
};

// ===================== scratch (device globals; allocation-free) =====================
__device__ __align__(16) float g_C1[(size_t)C1_POS * C1_OC];      // conv1 out [pos][oc]
__device__ __align__(16) float g_P1[NIMG * P1_H * P1_W * 256];    // pooled NHWC
__device__ __align__(16) float g_C2[C2_POS * 128];
__device__ __align__(16) float g_A3[C3_POS * 512];
__device__ __align__(16) float g_C3[C3_POS * 128];
__device__ __align__(16) float g_F [NIMG * FC1_K];
__device__ __align__(16) float g_H1[NIMG * 4096];
__device__ __align__(16) float g_H2[NIMG * 4096];
__device__ __align__(16) float g_G0[NIMG * GATE];
__device__ __align__(16) float g_h[BATCH * HID];
__device__ __align__(16) float g_c[BATCH * HID];
__device__ __align__(16) float g_hid[NIMG * HID];
__device__ __align__(16) float g_b1[NIMG * 2048];                 // merged actor|critic layer1
__device__ __align__(16) float g_b2[NIMG * 1024];                 // merged actor|critic layer2
__device__ __align__(16) float g_w2t[128 * 16 * 256];             // conv2_w -> [oc][pq][c]
__device__ __align__(16) float g_w3t[128 * 4 * 128];              // conv3_w -> [oc][pq][c]
__device__ __align__(16) float g_cb[GATE];                        // bih + bhh
__device__ __align__(16) float g_part[(size_t)4 * C2_POS * 128];  // split-K partials (max case)
__device__ unsigned g_barrier;                                    // persistent-LSTM step barrier

__device__ __forceinline__ float leakyf(float z) { return z > 0.f ? z : 0.01f * z; }
__device__ __forceinline__ uint32_t f2tf(float x) {
    uint32_t r; asm("cvt.rna.tf32.f32 %0, %1;" : "=r"(r) : "f"(x)); return r;
}
__device__ __forceinline__ void split_tf32(float v, uint32_t& hi, uint32_t& lo) {
    hi = f2tf(v);
    lo = f2tf(v - __uint_as_float(hi));
}
__device__ __forceinline__ void mma_tf32(float& c0, float& c1, float& c2, float& c3,
                                         uint32_t a0, uint32_t a1, uint32_t a2, uint32_t a3,
                                         uint32_t b0, uint32_t b1)
{
    asm volatile("mma.sync.aligned.m16n8k8.row.col.f32.tf32.tf32.f32 "
                 "{%0,%1,%2,%3}, {%4,%5,%6,%7}, {%8,%9}, {%0,%1,%2,%3};"
                 : "+f"(c0), "+f"(c1), "+f"(c2), "+f"(c3)
                 : "r"(a0), "r"(a1), "r"(a2), "r"(a3), "r"(b0), "r"(b1));
}

// A-operand fetch: GM=0 linear, GM=1 im2col-from-x (conv1, with /255), GM=2 im2col-from-P1 (conv2).
// GM=1 uses two LDG.64: element offsets in this path are even (2j), NOT mult-of-4 -> float4 would trap.
template<int GM>
__device__ __forceinline__ float4 fetchA(const float* __restrict__ gA, int kg)
{
    if constexpr (GM == 1) {
        int p = kg >> 3, q = kg & 7;                 // k = p*8+q, 8x8 window
        const float* base = gA + p * IMG_W + q;
        float2 u = *(const float2*)(base);
        float2 v = *(const float2*)(base + 2);
        const float S = 1.f / 255.f;
        return make_float4(u.x * S, u.y * S, v.x * S, v.y * S);
    } else if constexpr (GM == 2) {
        int pq = kg >> 8, p = pq >> 2, q = pq & 3;   // k = pq*256 + c, NHWC gather (c mult of 4 -> aligned)
        return *(const float4*)(gA + (p * P1_W + q) * 256 + (kg & 255));
    } else {
        return *(const float4*)(gA + kg);
    }
}

// ===================== 3xTF32 tensor-core GEMM: C[M,N] = A[M,K] * B[N,K]^T =====================
// CTA tile 128x128 (8 warps, 2x4), warp tile 64x32 (4x4 m16n8k8 frags), k-chunk 16.
// hi/lo tf32 split; acc += a_hi*b_hi + a_hi*b_lo + a_lo*b_hi (~22-bit effective mantissa).
// Double-buffered smem (2 stages x 40KB dynamic); one barrier per chunk.
// Scalar [row][20] layout: frag-load banks (20g+tg) mod 32 cover all 32 -> conflict-free.
// GM selects A gather mode (see fetchA). Dual-operand (GM=0 only): blocks with
// blockIdx.x >= xHalf use A2/B2/bias2 (pre-adjusted). Split-K via blockIdx.z.
template<int GM>
__global__ void __launch_bounds__(256, 2) tgemm_t(
    const float* __restrict__ A, const float* __restrict__ B, float* __restrict__ C,
    int M, int N, int K, int lda, int ldb, int Kc, int nSplit,
    const float* __restrict__ bias, int act,
    const float* __restrict__ A2, const float* __restrict__ B2,
    const float* __restrict__ bias2, int xHalf)
{
    extern __shared__ uint32_t dsm[];   // 2 stages x 4 arrays x 128*20 words = 81920 B
    const int STG = 10240;

    const int s = blockIdx.z;
    const int tid = threadIdx.x;
    const int warp = tid >> 5, lane = tid & 31;
    const int g = lane >> 2, tg = lane & 3;
    const int wm = (warp >> 2) * 64;
    const int wn = (warp & 3) * 32;

    const int sm = tid >> 1;                    // staging row 0..127
    const int sk = (tid & 1) * 8;               // staging k offset 0 or 8

    const float* biasUse = bias;
    const float* gA;
    const float* gB;
    if constexpr (GM == 0) {
        const float* Abase = (A2 && blockIdx.x >= xHalf) ? A2 : A;
        const float* Bbase = (B2 && blockIdx.x >= xHalf) ? B2 : B;
        if (bias2 && blockIdx.x >= xHalf) biasUse = bias2;
        gA = Abase + (size_t)(blockIdx.y * 128 + sm) * lda;
        gB = Bbase + (size_t)(blockIdx.x * 128 + sm) * ldb;
    } else if constexpr (GM == 1) {
        int pos = blockIdx.y * 128 + sm;        // n*2013 + i*61 + j
        int n = pos / (C1_H * C1_W), r = pos % (C1_H * C1_W);
        int i = r / C1_W, j = r % C1_W;
        gA = A + ((size_t)(n * IMG_H + 2 * i) * IMG_W + 2 * j);
        gB = B + (size_t)(blockIdx.x * 128 + sm) * ldb;
    } else {
        int pos = blockIdx.y * 128 + sm;        // n*78 + i*13 + j
        int n = pos / (C2_H * C2_W), r = pos % (C2_H * C2_W);
        int i = r / C2_W, j = r % C2_W;
        gA = A + ((size_t)(n * P1_H + 2 * i) * P1_W + 2 * j) * 256;
        gB = B + (size_t)(blockIdx.x * 128 + sm) * ldb;
    }

    float acc[4][4][4];
#pragma unroll
    for (int i = 0; i < 4; i++)
#pragma unroll
        for (int j = 0; j < 4; j++)
#pragma unroll
            for (int r = 0; r < 4; r++) acc[i][j][r] = 0.f;

    const int kgBase = s * Kc + sk;
    float4 va0 = fetchA<GM>(gA, kgBase);
    float4 va1 = fetchA<GM>(gA, kgBase + 4);
    float4 vb0 = *(const float4*)(gB + kgBase);
    float4 vb1 = *(const float4*)(gB + kgBase + 4);

    int buf = 0;
    for (int k0 = 0; k0 < Kc; k0 += 16, buf ^= 1) {
        uint32_t* sAh = dsm + buf * STG;
        uint32_t* sAl = sAh + 2560;
        uint32_t* sBh = sAh + 5120;
        uint32_t* sBl = sAh + 7680;

        {
            uint32_t h0, h1, h2, h3, l0, l1, l2, l3;
            split_tf32(va0.x, h0, l0); split_tf32(va0.y, h1, l1);
            split_tf32(va0.z, h2, l2); split_tf32(va0.w, h3, l3);
            *(uint4*)&sAh[sm * 20 + sk] = make_uint4(h0, h1, h2, h3);
            *(uint4*)&sAl[sm * 20 + sk] = make_uint4(l0, l1, l2, l3);
            split_tf32(va1.x, h0, l0); split_tf32(va1.y, h1, l1);
            split_tf32(va1.z, h2, l2); split_tf32(va1.w, h3, l3);
            *(uint4*)&sAh[sm * 20 + sk + 4] = make_uint4(h0, h1, h2, h3);
            *(uint4*)&sAl[sm * 20 + sk + 4] = make_uint4(l0, l1, l2, l3);
            split_tf32(vb0.x, h0, l0); split_tf32(vb0.y, h1, l1);
            split_tf32(vb0.z, h2, l2); split_tf32(vb0.w, h3, l3);
            *(uint4*)&sBh[sm * 20 + sk] = make_uint4(h0, h1, h2, h3);
            *(uint4*)&sBl[sm * 20 + sk] = make_uint4(l0, l1, l2, l3);
            split_tf32(vb1.x, h0, l0); split_tf32(vb1.y, h1, l1);
            split_tf32(vb1.z, h2, l2); split_tf32(vb1.w, h3, l3);
            *(uint4*)&sBh[sm * 20 + sk + 4] = make_uint4(h0, h1, h2, h3);
            *(uint4*)&sBl[sm * 20 + sk + 4] = make_uint4(l0, l1, l2, l3);
        }
        __syncthreads();   // single barrier per chunk (WAR to this buf is 2 iters away)

        if (k0 + 16 < Kc) {
            va0 = fetchA<GM>(gA, kgBase + k0 + 16);
            va1 = fetchA<GM>(gA, kgBase + k0 + 20);
            vb0 = *(const float4*)(gB + kgBase + k0 + 16);
            vb1 = *(const float4*)(gB + kgBase + k0 + 20);
        }

#pragma unroll
        for (int ko = 0; ko < 16; ko += 8) {
            uint32_t af[4][4], bf[4][2];
            // ---- pass 1: a_hi * b_hi ----
#pragma unroll
            for (int mf = 0; mf < 4; mf++) {
                int r0 = (wm + mf * 16 + g) * 20;
                af[mf][0] = sAh[r0 + ko + tg];
                af[mf][1] = sAh[r0 + 160 + ko + tg];
                af[mf][2] = sAh[r0 + ko + tg + 4];
                af[mf][3] = sAh[r0 + 160 + ko + tg + 4];
            }
#pragma unroll
            for (int nf = 0; nf < 4; nf++) {
                int n0 = (wn + nf * 8 + g) * 20;
                bf[nf][0] = sBh[n0 + ko + tg];
                bf[nf][1] = sBh[n0 + ko + tg + 4];
            }
#pragma unroll
            for (int mf = 0; mf < 4; mf++)
#pragma unroll
                for (int nf = 0; nf < 4; nf++)
                    mma_tf32(acc[mf][nf][0], acc[mf][nf][1], acc[mf][nf][2], acc[mf][nf][3],
                             af[mf][0], af[mf][1], af[mf][2], af[mf][3],
                             bf[nf][0], bf[nf][1]);
            // ---- pass 2: a_hi * b_lo ----
#pragma unroll
            for (int nf = 0; nf < 4; nf++) {
                int n0 = (wn + nf * 8 + g) * 20;
                bf[nf][0] = sBl[n0 + ko + tg];
                bf[nf][1] = sBl[n0 + ko + tg + 4];
            }
#pragma unroll
            for (int mf = 0; mf < 4; mf++)
#pragma unroll
                for (int nf = 0; nf < 4; nf++)
                    mma_tf32(acc[mf][nf][0], acc[mf][nf][1], acc[mf][nf][2], acc[mf][nf][3],
                             af[mf][0], af[mf][1], af[mf][2], af[mf][3],
                             bf[nf][0], bf[nf][1]);
            // ---- pass 3: a_lo * b_hi ----
#pragma unroll
            for (int mf = 0; mf < 4; mf++) {
                int r0 = (wm + mf * 16 + g) * 20;
                af[mf][0] = sAl[r0 + ko + tg];
                af[mf][1] = sAl[r0 + 160 + ko + tg];
                af[mf][2] = sAl[r0 + ko + tg + 4];
                af[mf][3] = sAl[r0 + 160 + ko + tg + 4];
            }
#pragma unroll
            for (int nf = 0; nf < 4; nf++) {
                int n0 = (wn + nf * 8 + g) * 20;
                bf[nf][0] = sBh[n0 + ko + tg];
                bf[nf][1] = sBh[n0 + ko + tg + 4];
            }
#pragma unroll
            for (int mf = 0; mf < 4; mf++)
#pragma unroll
                for (int nf = 0; nf < 4; nf++)
                    mma_tf32(acc[mf][nf][0], acc[mf][nf][1], acc[mf][nf][2], acc[mf][nf][3],
                             af[mf][0], af[mf][1], af[mf][2], af[mf][3],
                             bf[nf][0], bf[nf][1]);
        }
    }

    // epilogue
    const int rowBase = blockIdx.y * 128 + wm + g;
    const int colBase = blockIdx.x * 128 + wn + tg * 2;
    if (nSplit > 1) {
        float* Cp = C + (size_t)s * M * N;
#pragma unroll
        for (int mf = 0; mf < 4; mf++)
#pragma unroll
            for (int nf = 0; nf < 4; nf++) {
                int row = rowBase + mf * 16;
                int col = colBase + nf * 8;
                *(float2*)&Cp[(size_t)row * N + col]       = make_float2(acc[mf][nf][0], acc[mf][nf][1]);
                *(float2*)&Cp[(size_t)(row + 8) * N + col] = make_float2(acc[mf][nf][2], acc[mf][nf][3]);
            }
    } else {
#pragma unroll
        for (int mf = 0; mf < 4; mf++)
#pragma unroll
            for (int nf = 0; nf < 4; nf++) {
                int row = rowBase + mf * 16;
                int col = colBase + nf * 8;
                float v0 = acc[mf][nf][0], v1 = acc[mf][nf][1];
                float v2 = acc[mf][nf][2], v3 = acc[mf][nf][3];
                if (biasUse) {
                    float b0 = biasUse[col], b1 = biasUse[col + 1];
                    v0 += b0; v1 += b1; v2 += b0; v3 += b1;
                }
                if (act) { v0 = leakyf(v0); v1 = leakyf(v1); v2 = leakyf(v2); v3 = leakyf(v3); }
                *(float2*)&C[(size_t)row * N + col]       = make_float2(v0, v1);
                *(float2*)&C[(size_t)(row + 8) * N + col] = make_float2(v2, v3);
            }
    }
}

__global__ void reduce_k(const float* __restrict__ P, float* __restrict__ C,
                         int MN, int N, int S, const float* __restrict__ bias, int act,
                         const float* __restrict__ bias2, int colSplit)
{
    int idx = blockIdx.x * 256 + threadIdx.x;
    if (idx >= MN) return;
    float v = 0.f;
    for (int s = 0; s < S; s++) v += P[(size_t)s * MN + idx];
    int col = idx % N;
    if (bias2 && col >= colSplit) v += bias2[col - colSplit];
    else if (bias) v += bias[col];
    if (act) v = leakyf(v);
    C[idx] = v;
}

// ===================== layer-specific kernels =====================
__global__ void pool1_k(const float* __restrict__ conv1_b)
{
    int idx = blockIdx.x * 256 + threadIdx.x;                 // NHWC output
    if (idx >= NIMG * P1_H * P1_W * 256) return;
    int c = idx & 255, r = idx >> 8;
    int x = r % P1_W; r /= P1_W;
    int y = r % P1_H; int n = r / P1_H;
    float m = -3.4e38f;
#pragma unroll
    for (int p = 0; p < 4; p++)
#pragma unroll
        for (int q = 0; q < 4; q++) {
            int pos = (n * C1_H + 2 * y + p) * C1_W + (2 * x + q);
            float v = g_C1[(size_t)pos * 256 + c];
            m = fmaxf(m, v);
        }
    g_P1[idx] = leakyf(m + conv1_b[c]);
}

// merged prep: w2 transpose + w3 transpose + combined lstm bias
__global__ void prep_k(const float* __restrict__ w2, const float* __restrict__ w3,
                       const float* __restrict__ bih, const float* __restrict__ bhh)
{
    int idx = blockIdx.x * 256 + threadIdx.x;
    if (idx < 128 * 16 * 256) {   // w2t: [oc][c][pq] -> [oc][pq][c]
        int c = idx & 255, r = idx >> 8;
        int pq = r & 15, oc = r >> 4;
        g_w2t[idx] = w2[((size_t)oc * 256 + c) * 16 + pq];
    }
    if (idx < 128 * 4 * 128) {    // w3t
        int c = idx & 127, r = idx >> 7;
        int pq = r & 3, oc = r >> 2;
        g_w3t[idx] = w3[((size_t)oc * 128 + c) * 4 + pq];
    }
    if (idx < GATE) g_cb[idx] = bih[idx] + bhh[idx];
}

__global__ void im2col3_k()
{
    int idx = blockIdx.x * 256 + threadIdx.x;
    if (idx >= C3_POS * 512) return;
    int c = idx & 127, r = idx >> 7;
    int pq = r & 3, pos3 = r >> 2;
    int p = pq >> 1, q = pq & 1;
    int n = pos3 / (C3_H * C3_W), rem = pos3 % (C3_H * C3_W);
    int i = rem / C3_W, j = rem % C3_W;
    g_A3[idx] = g_C2[((size_t)(n * C2_H + i + p) * C2_W + (j + q)) * 128 + c];
}

__global__ void flatten_k() // [pos][c] -> [n][c*60 + i*12 + j]
{
    int idx = blockIdx.x * 256 + threadIdx.x;
    if (idx >= NIMG * FC1_K) return;
    int n = idx / FC1_K, r = idx % FC1_K;
    int c = r / 60, t = r % 60;
    int i = t / 12, j = t % 12;
    g_F[idx] = g_C3[(size_t)((n * C3_H + i) * C3_W + j) * 128 + c];
}

__global__ void init_hc_k(const float* __restrict__ h0, const float* __restrict__ c0)
{
    int i = blockIdx.x * 256 + threadIdx.x;
    if (i == 0) g_barrier = 0u;
    if (i < BATCH * HID) { g_h[i] = h0[i]; g_c[i] = c0[i]; }
}

// ===== persistent fused LSTM: single launch, internal t-loop with software global barrier.
// grid = 256 blocks x 256 thr (warp per hidden unit); residency guaranteed (2 CTA/SM min).
__global__ void __launch_bounds__(256, 2) lstm_persist_k(const float* __restrict__ whh,
                                                         const float* __restrict__ done)
{
    __shared__ float4 hs[BATCH * 512];
    const int tid = threadIdx.x;
    const int warp = tid >> 5, lane = tid & 31;
    const int k = blockIdx.x * 8 + warp;                  // hidden unit
    const float4* w0 = (const float4*)(whh + (size_t)(k          ) * HID);
    const float4* w1 = (const float4*)(whh + (size_t)(k + 1 * HID) * HID);
    const float4* w2 = (const float4*)(whh + (size_t)(k + 2 * HID) * HID);
    const float4* w3 = (const float4*)(whh + (size_t)(k + 3 * HID) * HID);

    for (int t = 0; t < TSTEPS; t++) {
        const float4* h4 = (const float4*)((t == 0) ? g_h : g_hid + (size_t)(t - 1) * 4 * HID);
        float m0 = 1.f - done[t * 4 + 0];
        float m1 = 1.f - done[t * 4 + 1];
        float m2 = 1.f - done[t * 4 + 2];
        float m3 = 1.f - done[t * 4 + 3];
        for (int u = tid; u < BATCH * 512; u += 256) {
            int b = u >> 9;
            float mb = (b == 0) ? m0 : (b == 1) ? m1 : (b == 2) ? m2 : m3;
            float4 v = h4[u];
            v.x *= mb; v.y *= mb; v.z *= mb; v.w *= mb;
            hs[u] = v;
        }
        __syncthreads();

        float sv[16];
#pragma unroll
        for (int i = 0; i < 16; i++) sv[i] = 0.f;

        for (int u = lane; u < 512; u += 32) {
            float4 a = hs[u], b = hs[512 + u], c = hs[1024 + u], d = hs[1536 + u];
            float4 w;
            w = w0[u];
            sv[0]  += w.x * a.x + w.y * a.y + w.z * a.z + w.w * a.w;
            sv[1]  += w.x * b.x + w.y * b.y + w.z * b.z + w.w * b.w;
            sv[2]  += w.x * c.x + w.y * c.y + w.z * c.z + w.w * c.w;
            sv[3]  += w.x * d.x + w.y * d.y + w.z * d.z + w.w * d.w;
            w = w1[u];
            sv[4]  += w.x * a.x + w.y * a.y + w.z * a.z + w.w * a.w;
            sv[5]  += w.x * b.x + w.y * b.y + w.z * b.z + w.w * b.w;
            sv[6]  += w.x * c.x + w.y * c.y + w.z * c.z + w.w * c.w;
            sv[7]  += w.x * d.x + w.y * d.y + w.z * d.z + w.w * d.w;
            w = w2[u];
            sv[8]  += w.x * a.x + w.y * a.y + w.z * a.z + w.w * a.w;
            sv[9]  += w.x * b.x + w.y * b.y + w.z * b.z + w.w * b.w;
            sv[10] += w.x * c.x + w.y * c.y + w.z * c.z + w.w * c.w;
            sv[11] += w.x * d.x + w.y * d.y + w.z * d.z + w.w * d.w;
            w = w3[u];
            sv[12] += w.x * a.x + w.y * a.y + w.z * a.z + w.w * a.w;
            sv[13] += w.x * b.x + w.y * b.y + w.z * b.z + w.w * b.w;
            sv[14] += w.x * c.x + w.y * c.y + w.z * c.z + w.w * c.w;
            sv[15] += w.x * d.x + w.y * d.y + w.z * d.z + w.w * d.w;
        }
#pragma unroll
        for (int i = 0; i < 16; i++) {
#pragma unroll
            for (int off = 16; off; off >>= 1)
                sv[i] += __shfl_down_sync(0xffffffffu, sv[i], off);
        }

        if (lane == 0) {
            const float mm[4] = { m0, m1, m2, m3 };
#pragma unroll
            for (int b = 0; b < 4; b++) {
                const float* G0r = g_G0 + (size_t)(t * 4 + b) * GATE;
                float gi = sv[0 + b]  + G0r[k];
                float gf = sv[4 + b]  + G0r[k + 2048];
                float gg = sv[8 + b]  + G0r[k + 4096];
                float go = sv[12 + b] + G0r[k + 6144];
                float i_ = 1.f / (1.f + expf(-gi));
                float f_ = 1.f / (1.f + expf(-gf));
                float g_ = tanhf(gg);
                float o_ = 1.f / (1.f + expf(-go));
                int idx = b * HID + k;
                float c = f_ * (g_c[idx] * mm[b]) + i_ * g_;
                g_c[idx] = c;
                g_hid[(size_t)(t * 4 + b) * HID + k] = o_ * tanhf(c);
            }
        }

        // device-wide step barrier (monotone counter; reset by init_hc_k each replay)
        __threadfence();
        __syncthreads();
        if (tid == 0) {
            atomicAdd(&g_barrier, 1u);
            unsigned target = (unsigned)(t + 1) * gridDim.x;
            while (*(volatile unsigned*)&g_barrier < target) __nanosleep(64);
        }
        __syncthreads();
    }
}

// warp-per-output gemv for tiny heads. out[n*Nout + o] = dot(A[n*lda .. +K], W[o]) + bias[o]
__global__ void gemv_k(const float* __restrict__ A, int lda,
                       const float* __restrict__ W,
                       const float* __restrict__ bias, float* __restrict__ out,
                       int Nout, int K)
{
    int gid = blockIdx.x * 8 + (threadIdx.x >> 5);
    if (gid >= NIMG * Nout) return;
    int lane = threadIdx.x & 31;
    int n = gid / Nout, o = gid - n * Nout;
    const float4* a = (const float4*)(A + (size_t)n * lda);
    const float4* w = (const float4*)(W + (size_t)o * K);
    int K4 = K >> 2;
    float s = 0.f;
    for (int u = lane; u < K4; u += 32) {
        float4 av = a[u], wv = w[u];
        s += av.x * wv.x + av.y * wv.y + av.z * wv.z + av.w * wv.w;
    }
#pragma unroll
    for (int off = 16; off; off >>= 1) s += __shfl_down_sync(0xffffffffu, s, off);
    if (lane == 0) out[(size_t)n * Nout + o] = s + bias[o];
}

__global__ void out_hc_k(float* __restrict__ out)
{
    int i = blockIdx.x * 256 + threadIdx.x;
    if (i < BATCH * HID) {
        out[4736 + i]  = g_hid[(size_t)(TSTEPS - 1) * 4 * HID + i];   // hn = outs[-1]
        out[12928 + i] = g_c[i];
    }
}

// ===================== host orchestration =====================
enum : int { TGEMM_SMEM = 81920 };

static void run_gemm2(const float* A, const float* A2, int lda,
                      const float* B, const float* B2adj, int ldb,
                      float* Cfinal, float* part,
                      int M, int N, int K, int S,
                      const float* bias, const float* bias2adj, int xHalf,
                      int act, int colSplit)
{
    dim3 grid(N / 128, M / 128, S);
    if (S == 1) {
        tgemm_t<0><<<grid, 256, TGEMM_SMEM>>>(A, B, Cfinal, M, N, K, lda, ldb, K, 1, bias, act,
                                              A2, B2adj, bias2adj, xHalf);
    } else {
        tgemm_t<0><<<grid, 256, TGEMM_SMEM>>>(A, B, part, M, N, K, lda, ldb, K / S, S, nullptr, 0,
                                              A2, B2adj, nullptr, xHalf);
        int MN = M * N;
        reduce_k<<<(MN + 255) / 256, 256>>>(part, Cfinal, MN, N, S, bias, act,
                                            bias2adj ? bias2adj + colSplit : nullptr, colSplit);
    }
}

static void run_gemm(const float* A, const float* B, float* Cfinal, float* part,
                     int M, int N, int K, int S, const float* bias, int act)
{
    run_gemm2(A, nullptr, K, B, nullptr, K, Cfinal, part, M, N, K, S,
              bias, nullptr, 1 << 30, act, 0);
}

extern "C" void kernel_launch(void* const* d_in, const int* in_sizes, int n_in,
                              void* d_out, int out_size)
{
    (void)in_sizes; (void)n_in; (void)out_size;
    const float* x        = (const float*)d_in[0];
    const float* done     = (const float*)d_in[1];
    const float* h0       = (const float*)d_in[2];
    const float* c0       = (const float*)d_in[3];
    const float* conv1_w  = (const float*)d_in[4];
    const float* conv1_b  = (const float*)d_in[5];
    const float* conv2_w  = (const float*)d_in[6];
    const float* conv2_b  = (const float*)d_in[7];
    const float* conv3_w  = (const float*)d_in[8];
    const float* conv3_b  = (const float*)d_in[9];
    const float* fc1_w    = (const float*)d_in[10];
    const float* fc1_b    = (const float*)d_in[11];
    const float* fc2_w    = (const float*)d_in[12];
    const float* fc2_b    = (const float*)d_in[13];
    const float* lstm_wih = (const float*)d_in[14];
    const float* lstm_whh = (const float*)d_in[15];
    const float* lstm_bih = (const float*)d_in[16];
    const float* lstm_bhh = (const float*)d_in[17];
    const float* a1_w = (const float*)d_in[18];
    const float* a1_b = (const float*)d_in[19];
    const float* a2_w = (const float*)d_in[20];
    const float* a2_b = (const float*)d_in[21];
    const float* a3_w = (const float*)d_in[22];
    const float* a3_b = (const float*)d_in[23];
    const float* v1_w = (const float*)d_in[24];
    const float* v1_b = (const float*)d_in[25];
    const float* v2_w = (const float*)d_in[26];
    const float* v2_b = (const float*)d_in[27];
    const float* v3_w = (const float*)d_in[28];
    const float* v3_b = (const float*)d_in[29];
    float* out = (float*)d_out;

    static int smemSet = 0;
    if (!smemSet) {
        cudaFuncSetAttribute(tgemm_t<0>, cudaFuncAttributeMaxDynamicSharedMemorySize, TGEMM_SMEM);
        cudaFuncSetAttribute(tgemm_t<1>, cudaFuncAttributeMaxDynamicSharedMemorySize, TGEMM_SMEM);
        cudaFuncSetAttribute(tgemm_t<2>, cudaFuncAttributeMaxDynamicSharedMemorySize, TGEMM_SMEM);
        smemSet = 1;
    }

    float *C1, *C2, *A3, *C3, *F, *H1, *H2, *G0, *cb, *b1, *b2, *hid, *part, *P1;
    float *w2t, *w3t;
    cudaGetSymbolAddress((void**)&C1, g_C1);
    cudaGetSymbolAddress((void**)&P1, g_P1);
    cudaGetSymbolAddress((void**)&C2, g_C2);
    cudaGetSymbolAddress((void**)&A3, g_A3);
    cudaGetSymbolAddress((void**)&C3, g_C3);
    cudaGetSymbolAddress((void**)&F,  g_F);
    cudaGetSymbolAddress((void**)&H1, g_H1);
    cudaGetSymbolAddress((void**)&H2, g_H2);
    cudaGetSymbolAddress((void**)&G0, g_G0);
    cudaGetSymbolAddress((void**)&cb, g_cb);
    cudaGetSymbolAddress((void**)&b1, g_b1);
    cudaGetSymbolAddress((void**)&b2, g_b2);
    cudaGetSymbolAddress((void**)&w2t, g_w2t);
    cudaGetSymbolAddress((void**)&w3t, g_w3t);
    cudaGetSymbolAddress((void**)&hid, g_hid);
    cudaGetSymbolAddress((void**)&part, g_part);

    // --- conv backbone ---
    // conv1: A gathered directly from x (im2col fused into GEMM)
    {
        dim3 grid(C1_OC / 128, C1_POS / 128, 1);
        tgemm_t<1><<<grid, 256, TGEMM_SMEM>>>(x, conv1_w, C1, C1_POS, C1_OC, 64, 64, 64, 64, 1,
                                              nullptr, 0, nullptr, nullptr, nullptr, 1 << 30);
    }
    pool1_k<<<(NIMG * P1_H * P1_W * 256 + 255) / 256, 256>>>(conv1_b);

    prep_k<<<(128 * 16 * 256 + 255) / 256, 256>>>(conv2_w, conv3_w, lstm_bih, lstm_bhh);

    // conv2: A gathered directly from P1 (im2col fused), split-K 4
    {
        dim3 grid(1, C2_POS / 128, 4);
        tgemm_t<2><<<grid, 256, TGEMM_SMEM>>>(P1, w2t, part, C2_POS, 128, 4096, 4096, 4096,
                                              1024, 4, nullptr, 0, nullptr, nullptr, nullptr, 1 << 30);
        int MN = C2_POS * 128;
        reduce_k<<<(MN + 255) / 256, 256>>>(part, C2, MN, 128, 4, conv2_b, 1, nullptr, 0);
    }

    im2col3_k<<<(C3_POS * 512 + 255) / 256, 256>>>();
    run_gemm(A3, w3t, C3, part, C3_POS, 128, 512, 2, conv3_b, 1);

    flatten_k<<<(NIMG * FC1_K + 255) / 256, 256>>>();

    // --- MLP ---
    run_gemm(F,  fc1_w, H1, part, NIMG, 4096, FC1_K, 8, fc1_b, 1);
    run_gemm(H1, fc2_w, H2, part, NIMG, 4096, 4096, 8, fc2_b, 1);

    // --- LSTM input projection for all T at once ---
    run_gemm(H2, lstm_wih, G0, part, NIMG, GATE, 4096, 4, cb, 0);

    // --- recurrence: single persistent launch ---
    init_hc_k<<<(BATCH * HID + 255) / 256, 256>>>(h0, c0);
    lstm_persist_k<<<HID / 8, 256>>>(lstm_whh, done);

    // --- merged actor|critic heads ---
    {
        const int xHalf = 8;  // 1024 / 128
        const float* v1w_adj = v1_w - (size_t)xHalf * 128 * 2048;
        const float* v1b_adj = v1_b - 1024;
        run_gemm2(hid, nullptr, 2048, a1_w, v1w_adj, 2048, b1, part,
                  NIMG, 2048, 2048, 16, a1_b, v1b_adj, xHalf, 1, 1024);
    }
    {
        const int xHalf = 4;  // 512 / 128
        const float* v2w_adj = v2_w - (size_t)xHalf * 128 * 1024;
        const float* v2b_adj = v2_b - 512;
        run_gemm2(b1, b1 + 1024, 2048, a2_w, v2w_adj, 1024, b2, part,
                  NIMG, 1024, 1024, 16, a2_b, v2b_adj, xHalf, 1, 512);
    }
    gemv_k<<<(NIMG * 36 + 7) / 8, 256>>>(b2, 1024, a3_w, a3_b, out, 36, 512);
    gemv_k<<<(NIMG * 1 + 7) / 8, 256>>>(b2 + 512, 1024, v3_w, v3_b, out + 4608, 1, 512);

    // --- hn, cn ---
    out_hc_k<<<(BATCH * HID + 255) / 256, 256>>>(out);
}

// round 17
// speedup vs baseline: 1.4916x; 1.0546x over previous
#include <cuda_runtime.h>
#include <math.h>
#include <stdint.h>

// ===================== dims =====================
enum : int {
    NIMG = 128, IMG_H = 72, IMG_W = 128,
    C1_OC = 256, C1_H = 33, C1_W = 61, C1_POS = NIMG * C1_H * C1_W,   // 257664
    P1_H = 15, P1_W = 29,
    C2_OC = 128, C2_H = 6, C2_W = 13, C2_POS = NIMG * C2_H * C2_W,    // 9984
    C3_OC = 128, C3_H = 5, C3_W = 12, C3_POS = NIMG * C3_H * C3_W,    // 7680
    FC1_N = 4096, FC1_K = 7680,
    HID = 2048, GATE = 8192,
    TSTEPS = 32, BATCH = 4,
};

// ===================== scratch (device globals; allocation-free) =====================
__device__ __align__(16) float g_C1[(size_t)C1_POS * C1_OC];      // conv1 out [pos][oc]
__device__ __align__(16) float g_P1[NIMG * P1_H * P1_W * 256];    // pooled NHWC
__device__ __align__(16) float g_C2[C2_POS * 128];
__device__ __align__(16) float g_A3[C3_POS * 512];
__device__ __align__(16) float g_C3[C3_POS * 128];
__device__ __align__(16) float g_F [NIMG * FC1_K];
__device__ __align__(16) float g_H1[NIMG * 4096];
__device__ __align__(16) float g_H2[NIMG * 4096];
__device__ __align__(16) float g_G0[NIMG * GATE];
__device__ __align__(16) float g_h[BATCH * HID];
__device__ __align__(16) float g_c[BATCH * HID];
__device__ __align__(16) float g_hid[NIMG * HID];
__device__ __align__(16) float g_b1[NIMG * 2048];                 // merged actor|critic layer1
__device__ __align__(16) float g_b2[NIMG * 1024];                 // merged actor|critic layer2
__device__ __align__(16) float g_w2t[128 * 16 * 256];             // conv2_w -> [oc][pq][c]
__device__ __align__(16) float g_w3t[128 * 4 * 128];              // conv3_w -> [oc][pq][c]
__device__ __align__(16) float g_cb[GATE];                        // bih + bhh
__device__ __align__(16) float g_part[(size_t)8 * C2_POS * 128];  // split-K partials (max: conv2 S=8)
__device__ unsigned g_barrier;                                    // persistent-LSTM step barrier

__device__ __forceinline__ float leakyf(float z) { return z > 0.f ? z : 0.01f * z; }
__device__ __forceinline__ uint32_t f2tf(float x) {
    uint32_t r; asm("cvt.rna.tf32.f32 %0, %1;" : "=r"(r) : "f"(x)); return r;
}
__device__ __forceinline__ void split_tf32(float v, uint32_t& hi, uint32_t& lo) {
    hi = f2tf(v);
    lo = f2tf(v - __uint_as_float(hi));
}
__device__ __forceinline__ void mma_tf32(float& c0, float& c1, float& c2, float& c3,
                                         uint32_t a0, uint32_t a1, uint32_t a2, uint32_t a3,
                                         uint32_t b0, uint32_t b1)
{
    asm volatile("mma.sync.aligned.m16n8k8.row.col.f32.tf32.tf32.f32 "
                 "{%0,%1,%2,%3}, {%4,%5,%6,%7}, {%8,%9}, {%0,%1,%2,%3};"
                 : "+f"(c0), "+f"(c1), "+f"(c2), "+f"(c3)
                 : "r"(a0), "r"(a1), "r"(a2), "r"(a3), "r"(b0), "r"(b1));
}

// A-operand fetch: GM=0 linear, GM=1 im2col-from-x (conv1, with /255), GM=2 im2col-from-P1 (conv2).
// GM=1 uses two LDG.64: element offsets in this path are even (2j), NOT mult-of-4 -> float4 would trap.
template<int GM>
__device__ __forceinline__ float4 fetchA(const float* __restrict__ gA, int kg)
{
    if constexpr (GM == 1) {
        int p = kg >> 3, q = kg & 7;                 // k = p*8+q, 8x8 window
        const float* base = gA + p * IMG_W + q;
        float2 u = *(const float2*)(base);
        float2 v = *(const float2*)(base + 2);
        const float S = 1.f / 255.f;
        return make_float4(u.x * S, u.y * S, v.x * S, v.y * S);
    } else if constexpr (GM == 2) {
        int pq = kg >> 8, p = pq >> 2, q = pq & 3;   // k = pq*256 + c, NHWC gather (c mult of 4 -> aligned)
        return *(const float4*)(gA + (p * P1_W + q) * 256 + (kg & 255));
    } else {
        return *(const float4*)(gA + kg);
    }
}

// ===================== 3xTF32 tensor-core GEMM: C[M,N] = A[M,K] * B[N,K]^T =====================
// CTA tile 128x128 (8 warps, 2x4), warp tile 64x32 (4x4 m16n8k8 frags), k-chunk 16.
// hi/lo tf32 split; acc += a_hi*b_hi + a_hi*b_lo + a_lo*b_hi (~22-bit effective mantissa).
// Double-buffered smem (2 stages x 40KB dynamic); one barrier per chunk.
// Scalar [row][20] layout: frag-load banks (20g+tg) mod 32 cover all 32 -> conflict-free.
// GM selects A gather mode (see fetchA). Dual-operand (GM=0 only): blocks with
// blockIdx.x >= xHalf use A2/B2/bias2 (pre-adjusted). Split-K via blockIdx.z.
template<int GM>
__global__ void __launch_bounds__(256, 2) tgemm_t(
    const float* __restrict__ A, const float* __restrict__ B, float* __restrict__ C,
    int M, int N, int K, int lda, int ldb, int Kc, int nSplit,
    const float* __restrict__ bias, int act,
    const float* __restrict__ A2, const float* __restrict__ B2,
    const float* __restrict__ bias2, int xHalf)
{
    extern __shared__ uint32_t dsm[];   // 2 stages x 4 arrays x 128*20 words = 81920 B
    const int STG = 10240;

    const int s = blockIdx.z;
    const int tid = threadIdx.x;
    const int warp = tid >> 5, lane = tid & 31;
    const int g = lane >> 2, tg = lane & 3;
    const int wm = (warp >> 2) * 64;
    const int wn = (warp & 3) * 32;

    const int sm = tid >> 1;                    // staging row 0..127
    const int sk = (tid & 1) * 8;               // staging k offset 0 or 8

    const float* biasUse = bias;
    const float* gA;
    const float* gB;
    if constexpr (GM == 0) {
        const float* Abase = (A2 && blockIdx.x >= xHalf) ? A2 : A;
        const float* Bbase = (B2 && blockIdx.x >= xHalf) ? B2 : B;
        if (bias2 && blockIdx.x >= xHalf) biasUse = bias2;
        gA = Abase + (size_t)(blockIdx.y * 128 + sm) * lda;
        gB = Bbase + (size_t)(blockIdx.x * 128 + sm) * ldb;
    } else if constexpr (GM == 1) {
        int pos = blockIdx.y * 128 + sm;        // n*2013 + i*61 + j
        int n = pos / (C1_H * C1_W), r = pos % (C1_H * C1_W);
        int i = r / C1_W, j = r % C1_W;
        gA = A + ((size_t)(n * IMG_H + 2 * i) * IMG_W + 2 * j);
        gB = B + (size_t)(blockIdx.x * 128 + sm) * ldb;
    } else {
        int pos = blockIdx.y * 128 + sm;        // n*78 + i*13 + j
        int n = pos / (C2_H * C2_W), r = pos % (C2_H * C2_W);
        int i = r / C2_W, j = r % C2_W;
        gA = A + ((size_t)(n * P1_H + 2 * i) * P1_W + 2 * j) * 256;
        gB = B + (size_t)(blockIdx.x * 128 + sm) * ldb;
    }

    float acc[4][4][4];
#pragma unroll
    for (int i = 0; i < 4; i++)
#pragma unroll
        for (int j = 0; j < 4; j++)
#pragma unroll
            for (int r = 0; r < 4; r++) acc[i][j][r] = 0.f;

    const int kgBase = s * Kc + sk;
    float4 va0 = fetchA<GM>(gA, kgBase);
    float4 va1 = fetchA<GM>(gA, kgBase + 4);
    float4 vb0 = *(const float4*)(gB + kgBase);
    float4 vb1 = *(const float4*)(gB + kgBase + 4);

    int buf = 0;
    for (int k0 = 0; k0 < Kc; k0 += 16, buf ^= 1) {
        uint32_t* sAh = dsm + buf * STG;
        uint32_t* sAl = sAh + 2560;
        uint32_t* sBh = sAh + 5120;
        uint32_t* sBl = sAh + 7680;

        {
            uint32_t h0, h1, h2, h3, l0, l1, l2, l3;
            split_tf32(va0.x, h0, l0); split_tf32(va0.y, h1, l1);
            split_tf32(va0.z, h2, l2); split_tf32(va0.w, h3, l3);
            *(uint4*)&sAh[sm * 20 + sk] = make_uint4(h0, h1, h2, h3);
            *(uint4*)&sAl[sm * 20 + sk] = make_uint4(l0, l1, l2, l3);
            split_tf32(va1.x, h0, l0); split_tf32(va1.y, h1, l1);
            split_tf32(va1.z, h2, l2); split_tf32(va1.w, h3, l3);
            *(uint4*)&sAh[sm * 20 + sk + 4] = make_uint4(h0, h1, h2, h3);
            *(uint4*)&sAl[sm * 20 + sk + 4] = make_uint4(l0, l1, l2, l3);
            split_tf32(vb0.x, h0, l0); split_tf32(vb0.y, h1, l1);
            split_tf32(vb0.z, h2, l2); split_tf32(vb0.w, h3, l3);
            *(uint4*)&sBh[sm * 20 + sk] = make_uint4(h0, h1, h2, h3);
            *(uint4*)&sBl[sm * 20 + sk] = make_uint4(l0, l1, l2, l3);
            split_tf32(vb1.x, h0, l0); split_tf32(vb1.y, h1, l1);
            split_tf32(vb1.z, h2, l2); split_tf32(vb1.w, h3, l3);
            *(uint4*)&sBh[sm * 20 + sk + 4] = make_uint4(h0, h1, h2, h3);
            *(uint4*)&sBl[sm * 20 + sk + 4] = make_uint4(l0, l1, l2, l3);
        }
        __syncthreads();   // single barrier per chunk (WAR to this buf is 2 iters away)

        if (k0 + 16 < Kc) {
            va0 = fetchA<GM>(gA, kgBase + k0 + 16);
            va1 = fetchA<GM>(gA, kgBase + k0 + 20);
            vb0 = *(const float4*)(gB + kgBase + k0 + 16);
            vb1 = *(const float4*)(gB + kgBase + k0 + 20);
        }

#pragma unroll
        for (int ko = 0; ko < 16; ko += 8) {
            uint32_t af[4][4], bf[4][2];
            // ---- pass 1: a_hi * b_hi ----
#pragma unroll
            for (int mf = 0; mf < 4; mf++) {
                int r0 = (wm + mf * 16 + g) * 20;
                af[mf][0] = sAh[r0 + ko + tg];
                af[mf][1] = sAh[r0 + 160 + ko + tg];
                af[mf][2] = sAh[r0 + ko + tg + 4];
                af[mf][3] = sAh[r0 + 160 + ko + tg + 4];
            }
#pragma unroll
            for (int nf = 0; nf < 4; nf++) {
                int n0 = (wn + nf * 8 + g) * 20;
                bf[nf][0] = sBh[n0 + ko + tg];
                bf[nf][1] = sBh[n0 + ko + tg + 4];
            }
#pragma unroll
            for (int mf = 0; mf < 4; mf++)
#pragma unroll
                for (int nf = 0; nf < 4; nf++)
                    mma_tf32(acc[mf][nf][0], acc[mf][nf][1], acc[mf][nf][2], acc[mf][nf][3],
                             af[mf][0], af[mf][1], af[mf][2], af[mf][3],
                             bf[nf][0], bf[nf][1]);
            // ---- pass 2: a_hi * b_lo ----
#pragma unroll
            for (int nf = 0; nf < 4; nf++) {
                int n0 = (wn + nf * 8 + g) * 20;
                bf[nf][0] = sBl[n0 + ko + tg];
                bf[nf][1] = sBl[n0 + ko + tg + 4];
            }
#pragma unroll
            for (int mf = 0; mf < 4; mf++)
#pragma unroll
                for (int nf = 0; nf < 4; nf++)
                    mma_tf32(acc[mf][nf][0], acc[mf][nf][1], acc[mf][nf][2], acc[mf][nf][3],
                             af[mf][0], af[mf][1], af[mf][2], af[mf][3],
                             bf[nf][0], bf[nf][1]);
            // ---- pass 3: a_lo * b_hi ----
#pragma unroll
            for (int mf = 0; mf < 4; mf++) {
                int r0 = (wm + mf * 16 + g) * 20;
                af[mf][0] = sAl[r0 + ko + tg];
                af[mf][1] = sAl[r0 + 160 + ko + tg];
                af[mf][2] = sAl[r0 + ko + tg + 4];
                af[mf][3] = sAl[r0 + 160 + ko + tg + 4];
            }
#pragma unroll
            for (int nf = 0; nf < 4; nf++) {
                int n0 = (wn + nf * 8 + g) * 20;
                bf[nf][0] = sBh[n0 + ko + tg];
                bf[nf][1] = sBh[n0 + ko + tg + 4];
            }
#pragma unroll
            for (int mf = 0; mf < 4; mf++)
#pragma unroll
                for (int nf = 0; nf < 4; nf++)
                    mma_tf32(acc[mf][nf][0], acc[mf][nf][1], acc[mf][nf][2], acc[mf][nf][3],
                             af[mf][0], af[mf][1], af[mf][2], af[mf][3],
                             bf[nf][0], bf[nf][1]);
        }
    }

    // epilogue
    const int rowBase = blockIdx.y * 128 + wm + g;
    const int colBase = blockIdx.x * 128 + wn + tg * 2;
    if (nSplit > 1) {
        float* Cp = C + (size_t)s * M * N;
#pragma unroll
        for (int mf = 0; mf < 4; mf++)
#pragma unroll
            for (int nf = 0; nf < 4; nf++) {
                int row = rowBase + mf * 16;
                int col = colBase + nf * 8;
                *(float2*)&Cp[(size_t)row * N + col]       = make_float2(acc[mf][nf][0], acc[mf][nf][1]);
                *(float2*)&Cp[(size_t)(row + 8) * N + col] = make_float2(acc[mf][nf][2], acc[mf][nf][3]);
            }
    } else {
#pragma unroll
        for (int mf = 0; mf < 4; mf++)
#pragma unroll
            for (int nf = 0; nf < 4; nf++) {
                int row = rowBase + mf * 16;
                int col = colBase + nf * 8;
                float v0 = acc[mf][nf][0], v1 = acc[mf][nf][1];
                float v2 = acc[mf][nf][2], v3 = acc[mf][nf][3];
                if (biasUse) {
                    float b0 = biasUse[col], b1 = biasUse[col + 1];
                    v0 += b0; v1 += b1; v2 += b0; v3 += b1;
                }
                if (act) { v0 = leakyf(v0); v1 = leakyf(v1); v2 = leakyf(v2); v3 = leakyf(v3); }
                *(float2*)&C[(size_t)row * N + col]       = make_float2(v0, v1);
                *(float2*)&C[(size_t)(row + 8) * N + col] = make_float2(v2, v3);
            }
    }
}

__global__ void reduce_k(const float* __restrict__ P, float* __restrict__ C,
                         int MN, int N, int S, const float* __restrict__ bias, int act,
                         const float* __restrict__ bias2, int colSplit)
{
    int idx = blockIdx.x * 256 + threadIdx.x;
    if (idx >= MN) return;
    float v = 0.f;
    for (int s = 0; s < S; s++) v += P[(size_t)s * MN + idx];
    int col = idx % N;
    if (bias2 && col >= colSplit) v += bias2[col - colSplit];
    else if (bias) v += bias[col];
    if (act) v = leakyf(v);
    C[idx] = v;
}

// ===================== layer-specific kernels =====================
// pool over conv1 output, vectorized float4 across channels (c4 = group of 4 channels)
__global__ void pool1_k(const float* __restrict__ conv1_b)
{
    int idx = blockIdx.x * 256 + threadIdx.x;                 // NHWC/4 output
    if (idx >= NIMG * P1_H * P1_W * 64) return;
    int c4 = idx & 63;
    const int sp = idx >> 6;                                  // spatial index (PRESERVED)
    int r = sp;
    int x = r % P1_W; r /= P1_W;
    int y = r % P1_H; int n = r / P1_H;
    float4 m = make_float4(-3.4e38f, -3.4e38f, -3.4e38f, -3.4e38f);
#pragma unroll
    for (int p = 0; p < 4; p++)
#pragma unroll
        for (int q = 0; q < 4; q++) {
            int pos = (n * C1_H + 2 * y + p) * C1_W + (2 * x + q);
            float4 v = *(const float4*)&g_C1[(size_t)pos * 256 + c4 * 4];
            m.x = fmaxf(m.x, v.x); m.y = fmaxf(m.y, v.y);
            m.z = fmaxf(m.z, v.z); m.w = fmaxf(m.w, v.w);
        }
    float4 b = *(const float4*)(conv1_b + c4 * 4);
    float4 o = make_float4(leakyf(m.x + b.x), leakyf(m.y + b.y),
                           leakyf(m.z + b.z), leakyf(m.w + b.w));
    *(float4*)&g_P1[((size_t)sp << 8) + c4 * 4] = o;
}

// merged prep: w2 transpose + w3 transpose + combined lstm bias
__global__ void prep_k(const float* __restrict__ w2, const float* __restrict__ w3,
                       const float* __restrict__ bih, const float* __restrict__ bhh)
{
    int idx = blockIdx.x * 256 + threadIdx.x;
    if (idx < 128 * 16 * 256) {   // w2t: [oc][c][pq] -> [oc][pq][c]
        int c = idx & 255, r = idx >> 8;
        int pq = r & 15, oc = r >> 4;
        g_w2t[idx] = w2[((size_t)oc * 256 + c) * 16 + pq];
    }
    if (idx < 128 * 4 * 128) {    // w3t
        int c = idx & 127, r = idx >> 7;
        int pq = r & 3, oc = r >> 2;
        g_w3t[idx] = w3[((size_t)oc * 128 + c) * 4 + pq];
    }
    if (idx < GATE) g_cb[idx] = bih[idx] + bhh[idx];
}

__global__ void im2col3_k()
{
    int idx = blockIdx.x * 256 + threadIdx.x;
    if (idx >= C3_POS * 512) return;
    int c = idx & 127, r = idx >> 7;
    int pq = r & 3, pos3 = r >> 2;
    int p = pq >> 1, q = pq & 1;
    int n = pos3 / (C3_H * C3_W), rem = pos3 % (C3_H * C3_W);
    int i = rem / C3_W, j = rem % C3_W;
    g_A3[idx] = g_C2[((size_t)(n * C2_H + i + p) * C2_W + (j + q)) * 128 + c];
}

__global__ void flatten_k() // [pos][c] -> [n][c*60 + i*12 + j]
{
    int idx = blockIdx.x * 256 + threadIdx.x;
    if (idx >= NIMG * FC1_K) return;
    int n = idx / FC1_K, r = idx % FC1_K;
    int c = r / 60, t = r % 60;
    int i = t / 12, j = t % 12;
    g_F[idx] = g_C3[(size_t)((n * C3_H + i) * C3_W + j) * 128 + c];
}

__global__ void init_hc_k(const float* __restrict__ h0, const float* __restrict__ c0)
{
    int i = blockIdx.x * 256 + threadIdx.x;
    if (i == 0) g_barrier = 0u;
    if (i < BATCH * HID) { g_h[i] = h0[i]; g_c[i] = c0[i]; }
}

// ===== persistent fused LSTM: single launch, internal t-loop with software global barrier.
// grid = 256 blocks x 256 thr (warp per hidden unit); residency guaranteed (2 CTA/SM min).
__global__ void __launch_bounds__(256, 2) lstm_persist_k(const float* __restrict__ whh,
                                                         const float* __restrict__ done)
{
    __shared__ float4 hs[BATCH * 512];
    const int tid = threadIdx.x;
    const int warp = tid >> 5, lane = tid & 31;
    const int k = blockIdx.x * 8 + warp;                  // hidden unit
    const float4* w0 = (const float4*)(whh + (size_t)(k          ) * HID);
    const float4* w1 = (const float4*)(whh + (size_t)(k + 1 * HID) * HID);
    const float4* w2 = (const float4*)(whh + (size_t)(k + 2 * HID) * HID);
    const float4* w3 = (const float4*)(whh + (size_t)(k + 3 * HID) * HID);

    for (int t = 0; t < TSTEPS; t++) {
        const float4* h4 = (const float4*)((t == 0) ? g_h : g_hid + (size_t)(t - 1) * 4 * HID);
        float m0 = 1.f - done[t * 4 + 0];
        float m1 = 1.f - done[t * 4 + 1];
        float m2 = 1.f - done[t * 4 + 2];
        float m3 = 1.f - done[t * 4 + 3];
        for (int u = tid; u < BATCH * 512; u += 256) {
            int b = u >> 9;
            float mb = (b == 0) ? m0 : (b == 1) ? m1 : (b == 2) ? m2 : m3;
            float4 v = h4[u];
            v.x *= mb; v.y *= mb; v.z *= mb; v.w *= mb;
            hs[u] = v;
        }
        __syncthreads();

        float sv[16];
#pragma unroll
        for (int i = 0; i < 16; i++) sv[i] = 0.f;

        for (int u = lane; u < 512; u += 32) {
            float4 a = hs[u], b = hs[512 + u], c = hs[1024 + u], d = hs[1536 + u];
            float4 w;
            w = w0[u];
            sv[0]  += w.x * a.x + w.y * a.y + w.z * a.z + w.w * a.w;
            sv[1]  += w.x * b.x + w.y * b.y + w.z * b.z + w.w * b.w;
            sv[2]  += w.x * c.x + w.y * c.y + w.z * c.z + w.w * c.w;
            sv[3]  += w.x * d.x + w.y * d.y + w.z * d.z + w.w * d.w;
            w = w1[u];
            sv[4]  += w.x * a.x + w.y * a.y + w.z * a.z + w.w * a.w;
            sv[5]  += w.x * b.x + w.y * b.y + w.z * b.z + w.w * b.w;
            sv[6]  += w.x * c.x + w.y * c.y + w.z * c.z + w.w * c.w;
            sv[7]  += w.x * d.x + w.y * d.y + w.z * d.z + w.w * d.w;
            w = w2[u];
            sv[8]  += w.x * a.x + w.y * a.y + w.z * a.z + w.w * a.w;
            sv[9]  += w.x * b.x + w.y * b.y + w.z * b.z + w.w * b.w;
            sv[10] += w.x * c.x + w.y * c.y + w.z * c.z + w.w * c.w;
            sv[11] += w.x * d.x + w.y * d.y + w.z * d.z + w.w * d.w;
            w = w3[u];
            sv[12] += w.x * a.x + w.y * a.y + w.z * a.z + w.w * a.w;
            sv[13] += w.x * b.x + w.y * b.y + w.z * b.z + w.w * b.w;
            sv[14] += w.x * c.x + w.y * c.y + w.z * c.z + w.w * c.w;
            sv[15] += w.x * d.x + w.y * d.y + w.z * d.z + w.w * d.w;
        }
#pragma unroll
        for (int i = 0; i < 16; i++) {
#pragma unroll
            for (int off = 16; off; off >>= 1)
                sv[i] += __shfl_down_sync(0xffffffffu, sv[i], off);
        }

        if (lane == 0) {
            const float mm[4] = { m0, m1, m2, m3 };
#pragma unroll
            for (int b = 0; b < 4; b++) {
                const float* G0r = g_G0 + (size_t)(t * 4 + b) * GATE;
                float gi = sv[0 + b]  + G0r[k];
                float gf = sv[4 + b]  + G0r[k + 2048];
                float gg = sv[8 + b]  + G0r[k + 4096];
                float go = sv[12 + b] + G0r[k + 6144];
                float i_ = 1.f / (1.f + expf(-gi));
                float f_ = 1.f / (1.f + expf(-gf));
                float g_ = tanhf(gg);
                float o_ = 1.f / (1.f + expf(-go));
                int idx = b * HID + k;
                float c = f_ * (g_c[idx] * mm[b]) + i_ * g_;
                g_c[idx] = c;
                g_hid[(size_t)(t * 4 + b) * HID + k] = o_ * tanhf(c);
            }
        }

        // device-wide step barrier (monotone counter; reset by init_hc_k each replay)
        __threadfence();
        __syncthreads();
        if (tid == 0) {
            atomicAdd(&g_barrier, 1u);
            unsigned target = (unsigned)(t + 1) * gridDim.x;
            while (*(volatile unsigned*)&g_barrier < target) __nanosleep(64);
        }
        __syncthreads();
    }
}

// warp-per-output gemv for tiny heads. out[n*Nout + o] = dot(A[n*lda .. +K], W[o]) + bias[o]
__global__ void gemv_k(const float* __restrict__ A, int lda,
                       const float* __restrict__ W,
                       const float* __restrict__ bias, float* __restrict__ out,
                       int Nout, int K)
{
    int gid = blockIdx.x * 8 + (threadIdx.x >> 5);
    if (gid >= NIMG * Nout) return;
    int lane = threadIdx.x & 31;
    int n = gid / Nout, o = gid - n * Nout;
    const float4* a = (const float4*)(A + (size_t)n * lda);
    const float4* w = (const float4*)(W + (size_t)o * K);
    int K4 = K >> 2;
    float s = 0.f;
    for (int u = lane; u < K4; u += 32) {
        float4 av = a[u], wv = w[u];
        s += av.x * wv.x + av.y * wv.y + av.z * wv.z + av.w * wv.w;
    }
#pragma unroll
    for (int off = 16; off; off >>= 1) s += __shfl_down_sync(0xffffffffu, s, off);
    if (lane == 0) out[(size_t)n * Nout + o] = s + bias[o];
}

__global__ void out_hc_k(float* __restrict__ out)
{
    int i = blockIdx.x * 256 + threadIdx.x;
    if (i < BATCH * HID) {
        out[4736 + i]  = g_hid[(size_t)(TSTEPS - 1) * 4 * HID + i];   // hn = outs[-1]
        out[12928 + i] = g_c[i];
    }
}

// ===================== host orchestration =====================
enum : int { TGEMM_SMEM = 81920 };

static void run_gemm2(const float* A, const float* A2, int lda,
                      const float* B, const float* B2adj, int ldb,
                      float* Cfinal, float* part,
                      int M, int N, int K, int S,
                      const float* bias, const float* bias2adj, int xHalf,
                      int act, int colSplit)
{
    dim3 grid(N / 128, M / 128, S);
    if (S == 1) {
        tgemm_t<0><<<grid, 256, TGEMM_SMEM>>>(A, B, Cfinal, M, N, K, lda, ldb, K, 1, bias, act,
                                              A2, B2adj, bias2adj, xHalf);
    } else {
        tgemm_t<0><<<grid, 256, TGEMM_SMEM>>>(A, B, part, M, N, K, lda, ldb, K / S, S, nullptr, 0,
                                              A2, B2adj, nullptr, xHalf);
        int MN = M * N;
        reduce_k<<<(MN + 255) / 256, 256>>>(part, Cfinal, MN, N, S, bias, act,
                                            bias2adj ? bias2adj + colSplit : nullptr, colSplit);
    }
}

static void run_gemm(const float* A, const float* B, float* Cfinal, float* part,
                     int M, int N, int K, int S, const float* bias, int act)
{
    run_gemm2(A, nullptr, K, B, nullptr, K, Cfinal, part, M, N, K, S,
              bias, nullptr, 1 << 30, act, 0);
}

extern "C" void kernel_launch(void* const* d_in, const int* in_sizes, int n_in,
                              void* d_out, int out_size)
{
    (void)in_sizes; (void)n_in; (void)out_size;
    const float* x        = (const float*)d_in[0];
    const float* done     = (const float*)d_in[1];
    const float* h0       = (const float*)d_in[2];
    const float* c0       = (const float*)d_in[3];
    const float* conv1_w  = (const float*)d_in[4];
    const float* conv1_b  = (const float*)d_in[5];
    const float* conv2_w  = (const float*)d_in[6];
    const float* conv2_b  = (const float*)d_in[7];
    const float* conv3_w  = (const float*)d_in[8];
    const float* conv3_b  = (const float*)d_in[9];
    const float* fc1_w    = (const float*)d_in[10];
    const float* fc1_b    = (const float*)d_in[11];
    const float* fc2_w    = (const float*)d_in[12];
    const float* fc2_b    = (const float*)d_in[13];
    const float* lstm_wih = (const float*)d_in[14];
    const float* lstm_whh = (const float*)d_in[15];
    const float* lstm_bih = (const float*)d_in[16];
    const float* lstm_bhh = (const float*)d_in[17];
    const float* a1_w = (const float*)d_in[18];
    const float* a1_b = (const float*)d_in[19];
    const float* a2_w = (const float*)d_in[20];
    const float* a2_b = (const float*)d_in[21];
    const float* a3_w = (const float*)d_in[22];
    const float* a3_b = (const float*)d_in[23];
    const float* v1_w = (const float*)d_in[24];
    const float* v1_b = (const float*)d_in[25];
    const float* v2_w = (const float*)d_in[26];
    const float* v2_b = (const float*)d_in[27];
    const float* v3_w = (const float*)d_in[28];
    const float* v3_b = (const float*)d_in[29];
    float* out = (float*)d_out;

    static int smemSet = 0;
    if (!smemSet) {
        cudaFuncSetAttribute(tgemm_t<0>, cudaFuncAttributeMaxDynamicSharedMemorySize, TGEMM_SMEM);
        cudaFuncSetAttribute(tgemm_t<1>, cudaFuncAttributeMaxDynamicSharedMemorySize, TGEMM_SMEM);
        cudaFuncSetAttribute(tgemm_t<2>, cudaFuncAttributeMaxDynamicSharedMemorySize, TGEMM_SMEM);
        smemSet = 1;
    }

    float *C1, *C2, *A3, *C3, *F, *H1, *H2, *G0, *cb, *b1, *b2, *hid, *part, *P1;
    float *w2t, *w3t;
    cudaGetSymbolAddress((void**)&C1, g_C1);
    cudaGetSymbolAddress((void**)&P1, g_P1);
    cudaGetSymbolAddress((void**)&C2, g_C2);
    cudaGetSymbolAddress((void**)&A3, g_A3);
    cudaGetSymbolAddress((void**)&C3, g_C3);
    cudaGetSymbolAddress((void**)&F,  g_F);
    cudaGetSymbolAddress((void**)&H1, g_H1);
    cudaGetSymbolAddress((void**)&H2, g_H2);
    cudaGetSymbolAddress((void**)&G0, g_G0);
    cudaGetSymbolAddress((void**)&cb, g_cb);
    cudaGetSymbolAddress((void**)&b1, g_b1);
    cudaGetSymbolAddress((void**)&b2, g_b2);
    cudaGetSymbolAddress((void**)&w2t, g_w2t);
    cudaGetSymbolAddress((void**)&w3t, g_w3t);
    cudaGetSymbolAddress((void**)&hid, g_hid);
    cudaGetSymbolAddress((void**)&part, g_part);

    // --- conv backbone ---
    // conv1: A gathered directly from x (im2col fused into GEMM)
    {
        dim3 grid(C1_OC / 128, C1_POS / 128, 1);
        tgemm_t<1><<<grid, 256, TGEMM_SMEM>>>(x, conv1_w, C1, C1_POS, C1_OC, 64, 64, 64, 64, 1,
                                              nullptr, 0, nullptr, nullptr, nullptr, 1 << 30);
    }
    pool1_k<<<(NIMG * P1_H * P1_W * 64 + 255) / 256, 256>>>(conv1_b);

    prep_k<<<(128 * 16 * 256 + 255) / 256, 256>>>(conv2_w, conv3_w, lstm_bih, lstm_bhh);

    // conv2: A gathered directly from P1 (im2col fused), split-K 8 (smaller blocks kill
    // the 312-vs-296-slot wave-quantization tail seen in ncu)
    {
        dim3 grid(1, C2_POS / 128, 8);
        tgemm_t<2><<<grid, 256, TGEMM_SMEM>>>(P1, w2t, part, C2_POS, 128, 4096, 4096, 4096,
                                              512, 8, nullptr, 0, nullptr, nullptr, nullptr, 1 << 30);
        int MN = C2_POS * 128;
        reduce_k<<<(MN + 255) / 256, 256>>>(part, C2, MN, 128, 8, conv2_b, 1, nullptr, 0);
    }

    im2col3_k<<<(C3_POS * 512 + 255) / 256, 256>>>();
    run_gemm(A3, w3t, C3, part, C3_POS, 128, 512, 4, conv3_b, 1);

    flatten_k<<<(NIMG * FC1_K + 255) / 256, 256>>>();

    // --- MLP ---
    run_gemm(F,  fc1_w, H1, part, NIMG, 4096, FC1_K, 8, fc1_b, 1);
    run_gemm(H1, fc2_w, H2, part, NIMG, 4096, 4096, 8, fc2_b, 1);

    // --- LSTM input projection for all T at once ---
    run_gemm(H2, lstm_wih, G0, part, NIMG, GATE, 4096, 4, cb, 0);

    // --- recurrence: single persistent launch ---
    init_hc_k<<<(BATCH * HID + 255) / 256, 256>>>(h0, c0);
    lstm_persist_k<<<HID / 8, 256>>>(lstm_whh, done);

    // --- merged actor|critic heads ---
    {
        const int xHalf = 8;  // 1024 / 128
        const float* v1w_adj = v1_w - (size_t)xHalf * 128 * 2048;
        const float* v1b_adj = v1_b - 1024;
        run_gemm2(hid, nullptr, 2048, a1_w, v1w_adj, 2048, b1, part,
                  NIMG, 2048, 2048, 16, a1_b, v1b_adj, xHalf, 1, 1024);
    }
    {
        const int xHalf = 4;  // 512 / 128
        const float* v2w_adj = v2_w - (size_t)xHalf * 128 * 1024;
        const float* v2b_adj = v2_b - 512;
        run_gemm2(b1, b1 + 1024, 2048, a2_w, v2w_adj, 1024, b2, part,
                  NIMG, 1024, 1024, 16, a2_b, v2b_adj, xHalf, 1, 512);
    }
    gemv_k<<<(NIMG * 36 + 7) / 8, 256>>>(b2, 1024, a3_w, a3_b, out, 36, 512);
    gemv_k<<<(NIMG * 1 + 7) / 8, 256>>>(b2 + 512, 1024, v3_w, v3_b, out + 4608, 1, 512);

    // --- hn, cn ---
    out_hc_k<<<(BATCH * HID + 255) / 256, 256>>>(out);
}